// round 1
// baseline (speedup 1.0000x reference)
#include <cuda_runtime.h>

// Problem constants
#define NIMG 256
#define RROOM 32
#define WW 8
#define HH 6
#define MXY 72
#define PIX (MXY*MXY)
#define EMBD 6
#define CIN 16
#define CMID 64

// Scratch (device globals; no allocation allowed)
__device__ float g_X0[NIMG*CIN*PIX];    // 21.2 MB
__device__ float g_XA[NIMG*CMID*PIX];   // 84.9 MB
__device__ float g_XB[NIMG*CMID*PIX];   // 84.9 MB
__device__ float g_feat[NIMG*RROOM*64]; // 2 MB
__device__ float g_S[NIMG*128];

// ---------------------------------------------------------------------------
// Stage 1: build input X0 (N,16,72,72) by GATHER over rooms (scatter-add in ref)
// ch 0..8 = sum_r room_tensor[r,c,w,h] at hit; ch9 = 1; ch10..15 = emb[r,e]*map
// ---------------------------------------------------------------------------
__global__ void k_build(const int* __restrict__ pos, const float* __restrict__ rt,
                        const float* __restrict__ emb, float* __restrict__ X0) {
    int n = blockIdx.x;
    __shared__ int s_px[RROOM], s_py[RROOM];
    __shared__ float s_emb[RROOM*EMBD];
    int t = threadIdx.x;
    if (t < RROOM) { s_px[t] = pos[(n*RROOM+t)*2]; s_py[t] = pos[(n*RROOM+t)*2+1]; }
    if (t < RROOM*EMBD) s_emb[t] = emb[t];
    __syncthreads();
    for (int pix = t; pix < PIX; pix += blockDim.x) {
        int i = pix / MXY, j = pix % MXY;
        float acc[9];
        float em[EMBD];
        #pragma unroll
        for (int c = 0; c < 9; c++) acc[c] = 0.f;
        #pragma unroll
        for (int e = 0; e < EMBD; e++) em[e] = 0.f;
        #pragma unroll 1
        for (int r = 0; r < RROOM; r++) {
            int w = i - s_px[r], h = j - s_py[r];
            if ((unsigned)w < (unsigned)WW && (unsigned)h < (unsigned)HH) {
                const float* rp = rt + (r*9)*(WW*HH) + w*HH + h;
                float m0 = rp[0];
                #pragma unroll
                for (int c = 0; c < 9; c++) acc[c] += rp[c*(WW*HH)];
                #pragma unroll
                for (int e = 0; e < EMBD; e++) em[e] += s_emb[r*EMBD+e] * m0;
            }
        }
        float* xp = X0 + (size_t)n*CIN*PIX + pix;
        #pragma unroll
        for (int c = 0; c < 9; c++) xp[c*PIX] = acc[c];
        xp[9*PIX] = 1.0f;
        #pragma unroll
        for (int e = 0; e < EMBD; e++) xp[(10+e)*PIX] = em[e];
    }
}

// ---------------------------------------------------------------------------
// conv1: 5x5, 16->64, pad 2, ReLU.
// Tile 12 rows x 24 cols. 288 threads: 4 oc-groups x 72 quads (2x2 pixels).
// Each thread: 16 oc x 4 pixels in registers.
// ---------------------------------------------------------------------------
__global__ __launch_bounds__(288, 1)
void k_conv5(const float* __restrict__ in, const float* __restrict__ w,
             const float* __restrict__ bias, float* __restrict__ out) {
    int tile = blockIdx.x;               // 0..17
    int n = blockIdx.y;
    int ti = (tile / 3) * 12;
    int tj = (tile % 3) * 24;
    int t = threadIdx.x;
    int ocg = t / 72;
    int p = t % 72;
    int qi = p / 12, qj = p % 12;
    int i0 = ti + qi*2, j0 = tj + qj*2;

    __shared__ float s_in[4][16][28];    // 4 ic, halo 2
    __shared__ float s_w[64][101];       // 4 ic * 25 per oc, pad to 101

    float acc[16][2][2];
    #pragma unroll
    for (int o = 0; o < 16; o++)
        #pragma unroll
        for (int a = 0; a < 2; a++)
            #pragma unroll
            for (int b = 0; b < 2; b++) acc[o][a][b] = 0.f;

    for (int c0 = 0; c0 < CIN; c0 += 4) {
        for (int idx = t; idx < 4*16*28; idx += 288) {
            int c = idx / (16*28);
            int rem = idx % (16*28);
            int li = rem / 28, lj = rem % 28;
            int gi = ti + li - 2, gj = tj + lj - 2;
            float v = 0.f;
            if ((unsigned)gi < 72u && (unsigned)gj < 72u)
                v = in[(((size_t)n*CIN + c0 + c)*72 + gi)*72 + gj];
            s_in[c][li][lj] = v;
        }
        for (int idx = t; idx < 64*100; idx += 288) {
            int oc = idx / 100, k = idx % 100;
            s_w[oc][k] = w[oc*400 + c0*25 + k];
        }
        __syncthreads();
        #pragma unroll 1
        for (int lic = 0; lic < 4; lic++) {
            float v[6][6];
            #pragma unroll
            for (int a = 0; a < 6; a++)
                #pragma unroll
                for (int b = 0; b < 6; b++)
                    v[a][b] = s_in[lic][qi*2 + a][qj*2 + b];
            #pragma unroll
            for (int oo = 0; oo < 16; oo++) {
                const float* wp = &s_w[ocg*16 + oo][lic*25];
                float wr[25];
                #pragma unroll
                for (int k = 0; k < 25; k++) wr[k] = wp[k];
                #pragma unroll
                for (int a = 0; a < 2; a++)
                    #pragma unroll
                    for (int b = 0; b < 2; b++) {
                        float s = acc[oo][a][b];
                        #pragma unroll
                        for (int ki = 0; ki < 5; ki++)
                            #pragma unroll
                            for (int kj = 0; kj < 5; kj++)
                                s += wr[ki*5+kj] * v[a+ki][b+kj];
                        acc[oo][a][b] = s;
                    }
            }
        }
        __syncthreads();
    }
    #pragma unroll
    for (int oo = 0; oo < 16; oo++) {
        int oc = ocg*16 + oo;
        float bv = bias[oc];
        #pragma unroll
        for (int a = 0; a < 2; a++)
            #pragma unroll
            for (int b = 0; b < 2; b++) {
                float r = acc[oo][a][b] + bv;
                out[(((size_t)n*CMID + oc)*72 + i0+a)*72 + j0+b] = r > 0.f ? r : 0.f;
            }
    }
}

// ---------------------------------------------------------------------------
// conv 3x3, 64->64, pad 1, ReLU. Same tiling scheme.
// ---------------------------------------------------------------------------
__global__ __launch_bounds__(288, 2)
void k_conv3(const float* __restrict__ in, const float* __restrict__ w,
             const float* __restrict__ bias, float* __restrict__ out) {
    int tile = blockIdx.x;
    int n = blockIdx.y;
    int ti = (tile / 3) * 12;
    int tj = (tile % 3) * 24;
    int t = threadIdx.x;
    int ocg = t / 72;
    int p = t % 72;
    int qi = p / 12, qj = p % 12;
    int i0 = ti + qi*2, j0 = tj + qj*2;

    __shared__ float s_in[8][14][26];    // 8 ic, halo 1
    __shared__ float s_w[64][73];        // 8 ic * 9 per oc, pad to 73

    float acc[16][2][2];
    #pragma unroll
    for (int o = 0; o < 16; o++)
        #pragma unroll
        for (int a = 0; a < 2; a++)
            #pragma unroll
            for (int b = 0; b < 2; b++) acc[o][a][b] = 0.f;

    for (int c0 = 0; c0 < CMID; c0 += 8) {
        for (int idx = t; idx < 8*14*26; idx += 288) {
            int c = idx / (14*26);
            int rem = idx % (14*26);
            int li = rem / 26, lj = rem % 26;
            int gi = ti + li - 1, gj = tj + lj - 1;
            float v = 0.f;
            if ((unsigned)gi < 72u && (unsigned)gj < 72u)
                v = in[(((size_t)n*CMID + c0 + c)*72 + gi)*72 + gj];
            s_in[c][li][lj] = v;
        }
        for (int idx = t; idx < 64*72; idx += 288) {
            int oc = idx / 72, k = idx % 72;
            s_w[oc][k] = w[oc*576 + c0*9 + k];
        }
        __syncthreads();
        #pragma unroll 2
        for (int lic = 0; lic < 8; lic++) {
            float v[4][4];
            #pragma unroll
            for (int a = 0; a < 4; a++)
                #pragma unroll
                for (int b = 0; b < 4; b++)
                    v[a][b] = s_in[lic][qi*2 + a][qj*2 + b];
            #pragma unroll
            for (int oo = 0; oo < 16; oo++) {
                const float* wp = &s_w[ocg*16 + oo][lic*9];
                float w0=wp[0], w1=wp[1], w2=wp[2], w3=wp[3], w4=wp[4],
                      w5=wp[5], w6=wp[6], w7=wp[7], w8=wp[8];
                #pragma unroll
                for (int a = 0; a < 2; a++)
                    #pragma unroll
                    for (int b = 0; b < 2; b++) {
                        float s = acc[oo][a][b];
                        s += w0*v[a  ][b] + w1*v[a  ][b+1] + w2*v[a  ][b+2];
                        s += w3*v[a+1][b] + w4*v[a+1][b+1] + w5*v[a+1][b+2];
                        s += w6*v[a+2][b] + w7*v[a+2][b+1] + w8*v[a+2][b+2];
                        acc[oo][a][b] = s;
                    }
            }
        }
        __syncthreads();
    }
    #pragma unroll
    for (int oo = 0; oo < 16; oo++) {
        int oc = ocg*16 + oo;
        float bv = bias[oc];
        #pragma unroll
        for (int a = 0; a < 2; a++)
            #pragma unroll
            for (int b = 0; b < 2; b++) {
                float r = acc[oo][a][b] + bv;
                out[(((size_t)n*CMID + oc)*72 + i0+a)*72 + j0+b] = r > 0.f ? r : 0.f;
            }
    }
}

// ---------------------------------------------------------------------------
// Per-room window pooling: feat[n,r,c] = sum_{w,h} X[n,c,px+w,py+h]*map / sum(map)
// ---------------------------------------------------------------------------
__global__ void k_feat(const float* __restrict__ X, const float* __restrict__ rt,
                       const int* __restrict__ pos, float* __restrict__ feat) {
    int b = blockIdx.x;            // n*32 + r
    int n = b >> 5, r = b & 31;
    int c = threadIdx.x;           // 0..63
    __shared__ float s_rm[48];
    if (c < 48) s_rm[c] = rt[r*9*48 + c];   // channel 0 = room_map
    __syncthreads();
    float rsum = 0.f;
    #pragma unroll
    for (int k = 0; k < 48; k++) rsum += s_rm[k];
    int px = pos[b*2], py = pos[b*2+1];
    const float* xp = X + (((size_t)n*CMID + c)*72 + px)*72 + py;
    float acc = 0.f;
    #pragma unroll
    for (int w = 0; w < WW; w++)
        #pragma unroll
        for (int h = 0; h < HH; h++)
            acc += s_rm[w*HH + h] * xp[w*72 + h];
    feat[b*64 + c] = acc / rsum;
}

// ---------------------------------------------------------------------------
// Per-room MLP 64->128->128 (ReLU both), summed over rooms -> S (N,128)
// ---------------------------------------------------------------------------
__global__ void k_room(const float* __restrict__ feat,
                       const float* __restrict__ w1, const float* __restrict__ b1,
                       const float* __restrict__ w2, const float* __restrict__ b2,
                       float* __restrict__ S) {
    int n = blockIdx.x;
    int o = threadIdx.x;  // 128
    __shared__ float s_f[64];
    __shared__ float s_h[128];
    float acc = 0.f;
    float bb1 = b1[o], bb2 = b2[o];
    for (int r = 0; r < RROOM; r++) {
        if (o < 64) s_f[o] = feat[(n*RROOM + r)*64 + o];
        __syncthreads();
        float a = bb1;
        #pragma unroll
        for (int c = 0; c < 64; c++) a += s_f[c] * w1[o*64 + c];
        s_h[o] = fmaxf(a, 0.f);
        __syncthreads();
        float z = bb2;
        #pragma unroll
        for (int c = 0; c < 128; c++) z += s_h[c] * w2[o*128 + c];
        acc += fmaxf(z, 0.f);
        __syncthreads();
    }
    S[n*128 + o] = acc;
}

// ---------------------------------------------------------------------------
// FC head: 128->256 ReLU -> 256->256
// ---------------------------------------------------------------------------
__global__ void k_fc(const float* __restrict__ S,
                     const float* __restrict__ wf1, const float* __restrict__ bf1,
                     const float* __restrict__ wf2, const float* __restrict__ bf2,
                     float* __restrict__ out) {
    int n = blockIdx.x;
    int o = threadIdx.x;  // 256
    __shared__ float s_in[128];
    __shared__ float s_h[256];
    if (o < 128) s_in[o] = S[n*128 + o];
    __syncthreads();
    float a = bf1[o];
    #pragma unroll
    for (int c = 0; c < 128; c++) a += s_in[c] * wf1[o*128 + c];
    s_h[o] = fmaxf(a, 0.f);
    __syncthreads();
    float z = bf2[o];
    #pragma unroll
    for (int c = 0; c < 256; c++) z += s_h[c] * wf2[o*256 + c];
    out[n*256 + o] = z;
}

extern "C" void kernel_launch(void* const* d_in, const int* in_sizes, int n_in,
                              void* d_out, int out_size) {
    const int*   pos = (const int*)d_in[0];
    const float* rt  = (const float*)d_in[1];
    const float* emb = (const float*)d_in[2];
    const float* w1  = (const float*)d_in[3];
    const float* b1  = (const float*)d_in[4];
    const float* w2  = (const float*)d_in[5];
    const float* b2  = (const float*)d_in[6];
    const float* w3  = (const float*)d_in[7];
    const float* b3  = (const float*)d_in[8];
    const float* wr1 = (const float*)d_in[9];
    const float* br1 = (const float*)d_in[10];
    const float* wr2 = (const float*)d_in[11];
    const float* br2 = (const float*)d_in[12];
    const float* wf1 = (const float*)d_in[13];
    const float* bf1 = (const float*)d_in[14];
    const float* wf2 = (const float*)d_in[15];
    const float* bf2 = (const float*)d_in[16];
    float* out = (float*)d_out;

    float *X0, *XA, *XB, *feat, *S;
    cudaGetSymbolAddress((void**)&X0, g_X0);
    cudaGetSymbolAddress((void**)&XA, g_XA);
    cudaGetSymbolAddress((void**)&XB, g_XB);
    cudaGetSymbolAddress((void**)&feat, g_feat);
    cudaGetSymbolAddress((void**)&S, g_S);

    k_build<<<NIMG, 256>>>(pos, rt, emb, X0);
    k_conv5<<<dim3(18, NIMG), 288>>>(X0, w1, b1, XA);
    k_conv3<<<dim3(18, NIMG), 288>>>(XA, w2, b2, XB);
    k_conv3<<<dim3(18, NIMG), 288>>>(XB, w3, b3, XA);
    k_feat<<<NIMG*RROOM, 64>>>(XA, rt, pos, feat);
    k_room<<<NIMG, 128>>>(feat, wr1, br1, wr2, br2, S);
    k_fc<<<NIMG, 256>>>(S, wf1, bf1, wf2, bf2, out);
}

// round 2
// speedup vs baseline: 2.1385x; 2.1385x over previous
#include <cuda_runtime.h>

// Problem constants
#define NIMG 256
#define RROOM 32
#define WW 8
#define HH 6
#define MXY 72
#define PIX (MXY*MXY)
#define EMBD 6
#define CIN 16
#define CMID 64

// Scratch (device globals; no allocation allowed)
__device__ float g_X0[NIMG*CIN*PIX];    // 21.2 MB
__device__ float g_XA[NIMG*CMID*PIX];   // 84.9 MB
__device__ float g_XB[NIMG*CMID*PIX];   // 84.9 MB
__device__ float g_feat[NIMG*RROOM*64]; // 2 MB
__device__ float g_S[NIMG*128];

// ---------------------------------------------------------------------------
// helpers
// ---------------------------------------------------------------------------
__device__ __forceinline__ unsigned f2tf32(float x) {
    unsigned u;
    asm("cvt.rna.tf32.f32 %0, %1;" : "=r"(u) : "f"(x));
    return u;
}

__device__ __forceinline__ void mma_tf32(float d[4], const unsigned a[4],
                                         unsigned b0, unsigned b1) {
    asm volatile(
        "mma.sync.aligned.m16n8k8.row.col.f32.tf32.tf32.f32 "
        "{%0,%1,%2,%3},{%4,%5,%6,%7},{%8,%9},{%0,%1,%2,%3};"
        : "+f"(d[0]), "+f"(d[1]), "+f"(d[2]), "+f"(d[3])
        : "r"(a[0]), "r"(a[1]), "r"(a[2]), "r"(a[3]), "r"(b0), "r"(b1));
}

// ---------------------------------------------------------------------------
// Stage 1: build input X0 (N,16,72,72) by GATHER over rooms
// ---------------------------------------------------------------------------
__global__ void k_build(const int* __restrict__ pos, const float* __restrict__ rt,
                        const float* __restrict__ emb, float* __restrict__ X0) {
    int n = blockIdx.x;
    __shared__ int s_px[RROOM], s_py[RROOM];
    __shared__ float s_emb[RROOM*EMBD];
    int t = threadIdx.x;
    if (t < RROOM) { s_px[t] = pos[(n*RROOM+t)*2]; s_py[t] = pos[(n*RROOM+t)*2+1]; }
    if (t < RROOM*EMBD) s_emb[t] = emb[t];
    __syncthreads();
    for (int pix = t; pix < PIX; pix += blockDim.x) {
        int i = pix / MXY, j = pix % MXY;
        float acc[9];
        float em[EMBD];
        #pragma unroll
        for (int c = 0; c < 9; c++) acc[c] = 0.f;
        #pragma unroll
        for (int e = 0; e < EMBD; e++) em[e] = 0.f;
        #pragma unroll 1
        for (int r = 0; r < RROOM; r++) {
            int w = i - s_px[r], h = j - s_py[r];
            if ((unsigned)w < (unsigned)WW && (unsigned)h < (unsigned)HH) {
                const float* rp = rt + (r*9)*(WW*HH) + w*HH + h;
                float m0 = rp[0];
                #pragma unroll
                for (int c = 0; c < 9; c++) acc[c] += rp[c*(WW*HH)];
                #pragma unroll
                for (int e = 0; e < EMBD; e++) em[e] += s_emb[r*EMBD+e] * m0;
            }
        }
        float* xp = X0 + (size_t)n*CIN*PIX + pix;
        #pragma unroll
        for (int c = 0; c < 9; c++) xp[c*PIX] = acc[c];
        xp[9*PIX] = 1.0f;
        #pragma unroll
        for (int e = 0; e < EMBD; e++) xp[(10+e)*PIX] = em[e];
    }
}

// ---------------------------------------------------------------------------
// conv3x3 64->64, pad 1, ReLU  —  tf32 mma.sync implicit GEMM
// Block: 9 warps (288 thr). Output tile: 4 rows x 72 cols = 288 px.
// Warp w handles pixel m16-tiles {2w, 2w+1}, all 64 oc.
// K = ic*9, processed in ic-chunks of 8 (k-chunk 72, 9 k8-steps).
// ---------------------------------------------------------------------------
__global__ __launch_bounds__(288, 2)
void k_conv3_mma(const float* __restrict__ in, const float* __restrict__ w,
                 const float* __restrict__ bias, float* __restrict__ out) {
    int tile = blockIdx.x;           // 0..17 row-tile
    int n = blockIdx.y;
    int r0 = tile * 4;
    int t = threadIdx.x;
    int warp = t >> 5, lane = t & 31;
    int g = lane >> 2, tig = lane & 3;

    // input tile: 8 ic x 6 rows (halo 1) x 74 cols (guard col each side)
    __shared__ unsigned s_x[8][6][74];
    // weights: rows k=0..71 (ic_local*9+tap), 64 oc, padded stride 72
    __shared__ unsigned s_w[72][72];

    float acc[2][8][4];
    #pragma unroll
    for (int a = 0; a < 2; a++)
        #pragma unroll
        for (int o = 0; o < 8; o++)
            #pragma unroll
            for (int k = 0; k < 4; k++) acc[a][o][k] = 0.f;

    // pixel coords for the 4 A-rows this thread touches: [tile2][gi]
    int prow[2][2], pcol[2][2];
    #pragma unroll
    for (int t2 = 0; t2 < 2; t2++)
        #pragma unroll
        for (int gi = 0; gi < 2; gi++) {
            int p = warp*32 + t2*16 + g + gi*8;   // 0..287
            prow[t2][gi] = p / 72;                // 0..3
            pcol[t2][gi] = p % 72;
        }

    const float* inb = in + (size_t)n * CMID * PIX;

    for (int c0 = 0; c0 < CMID; c0 += 8) {
        // --- load input tile (zero guard cols / out-of-image rows) ---
        for (int idx = t; idx < 8*6*74; idx += 288) {
            int c = idx / (6*74);
            int rem = idx % (6*74);
            int rr = rem / 74;
            int cidx = rem % 74;
            int cc = cidx - 1;
            int gi2 = r0 + rr - 1;
            float v = 0.f;
            if (cc >= 0 && cc < 72 && gi2 >= 0 && gi2 < 72)
                v = inb[(size_t)(c0 + c) * PIX + gi2*72 + cc];
            s_x[c][rr][cidx] = f2tf32(v);
        }
        // --- load weights: s_w[k][oc] ---
        for (int idx = t; idx < 72*64; idx += 288) {
            int k = idx >> 6, oc = idx & 63;
            s_w[k][oc] = f2tf32(w[oc*576 + c0*9 + k]);
        }
        __syncthreads();

        #pragma unroll 1
        for (int ks = 0; ks < 9; ks++) {
            int k0 = ks * 8;
            unsigned av[2][4];
            #pragma unroll
            for (int kk = 0; kk < 2; kk++) {
                int ki = k0 + tig + kk*4;
                int icl = ki / 9;
                int tap = ki - icl*9;
                int di = tap / 3, dj = tap % 3;   // 0..2 (halo offset baked in)
                #pragma unroll
                for (int t2 = 0; t2 < 2; t2++)
                    #pragma unroll
                    for (int gi = 0; gi < 2; gi++)
                        av[t2][kk*2 + gi] =
                            s_x[icl][prow[t2][gi] + di][pcol[t2][gi] + dj];
            }
            #pragma unroll
            for (int o = 0; o < 8; o++) {
                unsigned b0 = s_w[k0 + tig][o*8 + g];
                unsigned b1 = s_w[k0 + tig + 4][o*8 + g];
                mma_tf32(acc[0][o], av[0], b0, b1);
                mma_tf32(acc[1][o], av[1], b0, b1);
            }
        }
        __syncthreads();
    }

    // --- epilogue: bias + ReLU, NCHW store ---
    float* outb = out + (size_t)n * CMID * PIX;
    #pragma unroll
    for (int o = 0; o < 8; o++) {
        int oc0 = o*8 + 2*tig;
        float bv0 = bias[oc0], bv1 = bias[oc0 + 1];
        #pragma unroll
        for (int t2 = 0; t2 < 2; t2++) {
            #pragma unroll
            for (int gi = 0; gi < 2; gi++) {
                int gr = r0 + prow[t2][gi];
                int gc = pcol[t2][gi];
                float v0 = acc[t2][o][gi*2 + 0] + bv0;
                float v1 = acc[t2][o][gi*2 + 1] + bv1;
                outb[(size_t)oc0 * PIX + gr*72 + gc]       = v0 > 0.f ? v0 : 0.f;
                outb[(size_t)(oc0+1) * PIX + gr*72 + gc]   = v1 > 0.f ? v1 : 0.f;
            }
        }
    }
}

// ---------------------------------------------------------------------------
// conv5x5 16->64, pad 2, ReLU  —  tf32 mma.sync implicit GEMM
// ic-chunks of 4 (k-chunk 100, padded to 104 = 13 k8-steps).
// ---------------------------------------------------------------------------
__global__ __launch_bounds__(288, 2)
void k_conv5_mma(const float* __restrict__ in, const float* __restrict__ w,
                 const float* __restrict__ bias, float* __restrict__ out) {
    int tile = blockIdx.x;
    int n = blockIdx.y;
    int r0 = tile * 4;
    int t = threadIdx.x;
    int warp = t >> 5, lane = t & 31;
    int g = lane >> 2, tig = lane & 3;

    __shared__ unsigned s_x[4][8][76];   // 4 ic, 8 rows (halo 2), 76 cols (guard 2)
    __shared__ unsigned s_w[104][72];    // k rows (100 real + 4 zero pad), stride 72

    float acc[2][8][4];
    #pragma unroll
    for (int a = 0; a < 2; a++)
        #pragma unroll
        for (int o = 0; o < 8; o++)
            #pragma unroll
            for (int k = 0; k < 4; k++) acc[a][o][k] = 0.f;

    int prow[2][2], pcol[2][2];
    #pragma unroll
    for (int t2 = 0; t2 < 2; t2++)
        #pragma unroll
        for (int gi = 0; gi < 2; gi++) {
            int p = warp*32 + t2*16 + g + gi*8;
            prow[t2][gi] = p / 72;
            pcol[t2][gi] = p % 72;
        }

    const float* inb = in + (size_t)n * CIN * PIX;

    for (int c0 = 0; c0 < CIN; c0 += 4) {
        for (int idx = t; idx < 4*8*76; idx += 288) {
            int c = idx / (8*76);
            int rem = idx % (8*76);
            int rr = rem / 76;
            int cidx = rem % 76;
            int cc = cidx - 2;
            int gi2 = r0 + rr - 2;
            float v = 0.f;
            if (cc >= 0 && cc < 72 && gi2 >= 0 && gi2 < 72)
                v = inb[(size_t)(c0 + c) * PIX + gi2*72 + cc];
            s_x[c][rr][cidx] = f2tf32(v);
        }
        for (int idx = t; idx < 104*64; idx += 288) {
            int k = idx >> 6, oc = idx & 63;
            unsigned v = 0u;
            if (k < 100) v = f2tf32(w[oc*400 + c0*25 + k]);
            s_w[k][oc] = v;
        }
        __syncthreads();

        #pragma unroll 1
        for (int ks = 0; ks < 13; ks++) {
            int k0 = ks * 8;
            unsigned av[2][4];
            #pragma unroll
            for (int kk = 0; kk < 2; kk++) {
                int ki = k0 + tig + kk*4;
                int kiq = ki < 100 ? ki : 99;   // clamp; padded B rows are zero
                int icl = kiq / 25;
                int tap = kiq - icl*25;
                int di = tap / 5, dj = tap % 5;   // 0..4
                #pragma unroll
                for (int t2 = 0; t2 < 2; t2++)
                    #pragma unroll
                    for (int gi = 0; gi < 2; gi++)
                        av[t2][kk*2 + gi] =
                            s_x[icl][prow[t2][gi] + di][pcol[t2][gi] + dj];
            }
            #pragma unroll
            for (int o = 0; o < 8; o++) {
                unsigned b0 = s_w[k0 + tig][o*8 + g];
                unsigned b1 = s_w[k0 + tig + 4][o*8 + g];
                mma_tf32(acc[0][o], av[0], b0, b1);
                mma_tf32(acc[1][o], av[1], b0, b1);
            }
        }
        __syncthreads();
    }

    float* outb = out + (size_t)n * CMID * PIX;
    #pragma unroll
    for (int o = 0; o < 8; o++) {
        int oc0 = o*8 + 2*tig;
        float bv0 = bias[oc0], bv1 = bias[oc0 + 1];
        #pragma unroll
        for (int t2 = 0; t2 < 2; t2++) {
            #pragma unroll
            for (int gi = 0; gi < 2; gi++) {
                int gr = r0 + prow[t2][gi];
                int gc = pcol[t2][gi];
                float v0 = acc[t2][o][gi*2 + 0] + bv0;
                float v1 = acc[t2][o][gi*2 + 1] + bv1;
                outb[(size_t)oc0 * PIX + gr*72 + gc]       = v0 > 0.f ? v0 : 0.f;
                outb[(size_t)(oc0+1) * PIX + gr*72 + gc]   = v1 > 0.f ? v1 : 0.f;
            }
        }
    }
}

// ---------------------------------------------------------------------------
// Per-room window pooling
// ---------------------------------------------------------------------------
__global__ void k_feat(const float* __restrict__ X, const float* __restrict__ rt,
                       const int* __restrict__ pos, float* __restrict__ feat) {
    int b = blockIdx.x;            // n*32 + r
    int n = b >> 5, r = b & 31;
    int c = threadIdx.x;           // 0..63
    __shared__ float s_rm[48];
    if (c < 48) s_rm[c] = rt[r*9*48 + c];   // channel 0 = room_map
    __syncthreads();
    float rsum = 0.f;
    #pragma unroll
    for (int k = 0; k < 48; k++) rsum += s_rm[k];
    int px = pos[b*2], py = pos[b*2+1];
    const float* xp = X + (((size_t)n*CMID + c)*72 + px)*72 + py;
    float acc = 0.f;
    #pragma unroll
    for (int w = 0; w < WW; w++)
        #pragma unroll
        for (int h = 0; h < HH; h++)
            acc += s_rm[w*HH + h] * xp[w*72 + h];
    feat[b*64 + c] = acc / rsum;
}

// ---------------------------------------------------------------------------
// Per-room MLP 64->128->128 (ReLU both), summed over rooms -> S (N,128)
// ---------------------------------------------------------------------------
__global__ void k_room(const float* __restrict__ feat,
                       const float* __restrict__ w1, const float* __restrict__ b1,
                       const float* __restrict__ w2, const float* __restrict__ b2,
                       float* __restrict__ S) {
    int n = blockIdx.x;
    int o = threadIdx.x;  // 128
    __shared__ float s_f[64];
    __shared__ float s_h[128];
    float acc = 0.f;
    float bb1 = b1[o], bb2 = b2[o];
    for (int r = 0; r < RROOM; r++) {
        if (o < 64) s_f[o] = feat[(n*RROOM + r)*64 + o];
        __syncthreads();
        float a = bb1;
        #pragma unroll
        for (int c = 0; c < 64; c++) a += s_f[c] * w1[o*64 + c];
        s_h[o] = fmaxf(a, 0.f);
        __syncthreads();
        float z = bb2;
        #pragma unroll
        for (int c = 0; c < 128; c++) z += s_h[c] * w2[o*128 + c];
        acc += fmaxf(z, 0.f);
        __syncthreads();
    }
    S[n*128 + o] = acc;
}

// ---------------------------------------------------------------------------
// FC head: 128->256 ReLU -> 256->256
// ---------------------------------------------------------------------------
__global__ void k_fc(const float* __restrict__ S,
                     const float* __restrict__ wf1, const float* __restrict__ bf1,
                     const float* __restrict__ wf2, const float* __restrict__ bf2,
                     float* __restrict__ out) {
    int n = blockIdx.x;
    int o = threadIdx.x;  // 256
    __shared__ float s_in[128];
    __shared__ float s_h[256];
    if (o < 128) s_in[o] = S[n*128 + o];
    __syncthreads();
    float a = bf1[o];
    #pragma unroll
    for (int c = 0; c < 128; c++) a += s_in[c] * wf1[o*128 + c];
    s_h[o] = fmaxf(a, 0.f);
    __syncthreads();
    float z = bf2[o];
    #pragma unroll
    for (int c = 0; c < 256; c++) z += s_h[c] * wf2[o*256 + c];
    out[n*256 + o] = z;
}

extern "C" void kernel_launch(void* const* d_in, const int* in_sizes, int n_in,
                              void* d_out, int out_size) {
    const int*   pos = (const int*)d_in[0];
    const float* rt  = (const float*)d_in[1];
    const float* emb = (const float*)d_in[2];
    const float* w1  = (const float*)d_in[3];
    const float* b1  = (const float*)d_in[4];
    const float* w2  = (const float*)d_in[5];
    const float* b2  = (const float*)d_in[6];
    const float* w3  = (const float*)d_in[7];
    const float* b3  = (const float*)d_in[8];
    const float* wr1 = (const float*)d_in[9];
    const float* br1 = (const float*)d_in[10];
    const float* wr2 = (const float*)d_in[11];
    const float* br2 = (const float*)d_in[12];
    const float* wf1 = (const float*)d_in[13];
    const float* bf1 = (const float*)d_in[14];
    const float* wf2 = (const float*)d_in[15];
    const float* bf2 = (const float*)d_in[16];
    float* out = (float*)d_out;

    float *X0, *XA, *XB, *feat, *S;
    cudaGetSymbolAddress((void**)&X0, g_X0);
    cudaGetSymbolAddress((void**)&XA, g_XA);
    cudaGetSymbolAddress((void**)&XB, g_XB);
    cudaGetSymbolAddress((void**)&feat, g_feat);
    cudaGetSymbolAddress((void**)&S, g_S);

    k_build<<<NIMG, 256>>>(pos, rt, emb, X0);
    k_conv5_mma<<<dim3(18, NIMG), 288>>>(X0, w1, b1, XA);
    k_conv3_mma<<<dim3(18, NIMG), 288>>>(XA, w2, b2, XB);
    k_conv3_mma<<<dim3(18, NIMG), 288>>>(XB, w3, b3, XA);
    k_feat<<<NIMG*RROOM, 64>>>(XA, rt, pos, feat);
    k_room<<<NIMG, 128>>>(feat, wr1, br1, wr2, br2, S);
    k_fc<<<NIMG, 256>>>(S, wf1, bf1, wf2, bf2, out);
}

// round 3
// speedup vs baseline: 3.3904x; 1.5854x over previous
#include <cuda_runtime.h>

// Problem constants
#define NIMG 256
#define RROOM 32
#define WW 8
#define HH 6
#define MXY 72
#define PIX (MXY*MXY)
#define EMBD 6
#define CIN 16
#define CMID 64

// Scratch (device globals; no allocation allowed)
__device__ float g_X0[NIMG*CIN*PIX];    // 21.2 MB
__device__ float g_XA[NIMG*CMID*PIX];   // 84.9 MB
__device__ float g_XB[NIMG*CMID*PIX];   // 84.9 MB
__device__ float g_feat[NIMG*RROOM*64]; // 2 MB
__device__ float g_S[NIMG*128];
__device__ float g_wt[122880];          // transposed weights: w1t|w2t|wf1t|wf2t

// ---------------------------------------------------------------------------
// helpers
// ---------------------------------------------------------------------------
__device__ __forceinline__ unsigned f2tf32(float x) {
    unsigned u;
    asm("cvt.rna.tf32.f32 %0, %1;" : "=r"(u) : "f"(x));
    return u;
}

__device__ __forceinline__ void mma_tf32(float d[4], const unsigned a[4],
                                         unsigned b0, unsigned b1) {
    asm volatile(
        "mma.sync.aligned.m16n8k8.row.col.f32.tf32.tf32.f32 "
        "{%0,%1,%2,%3},{%4,%5,%6,%7},{%8,%9},{%0,%1,%2,%3};"
        : "+f"(d[0]), "+f"(d[1]), "+f"(d[2]), "+f"(d[3])
        : "r"(a[0]), "r"(a[1]), "r"(a[2]), "r"(a[3]), "r"(b0), "r"(b1));
}

// ---------------------------------------------------------------------------
// weight transpose prep (one-shot, independent of data path)
// layout in g_wt: w1t[64][128] @0, w2t[128][128] @8192,
//                 wf1t[128][256] @24576, wf2t[256][256] @57344
// ---------------------------------------------------------------------------
__global__ void k_prep(const float* __restrict__ w1, const float* __restrict__ w2,
                       const float* __restrict__ wf1, const float* __restrict__ wf2,
                       float* __restrict__ wt) {
    int t = blockIdx.x * blockDim.x + threadIdx.x;
    int stride = gridDim.x * blockDim.x;
    for (int i = t; i < 8192; i += stride)  { int c = i >> 7, o = i & 127; wt[i]         = w1[o*64 + c]; }
    for (int i = t; i < 16384; i += stride) { int c = i >> 7, o = i & 127; wt[8192 + i]  = w2[o*128 + c]; }
    for (int i = t; i < 32768; i += stride) { int c = i >> 8, o = i & 255; wt[24576 + i] = wf1[o*128 + c]; }
    for (int i = t; i < 65536; i += stride) { int c = i >> 8, o = i & 255; wt[57344 + i] = wf2[o*256 + c]; }
}

// ---------------------------------------------------------------------------
// Stage 1: build input X0 (N,16,72,72) by GATHER over rooms
// ---------------------------------------------------------------------------
__global__ void k_build(const int* __restrict__ pos, const float* __restrict__ rt,
                        const float* __restrict__ emb, float* __restrict__ X0) {
    int n = blockIdx.x;
    __shared__ int s_px[RROOM], s_py[RROOM];
    __shared__ float s_emb[RROOM*EMBD];
    int t = threadIdx.x;
    if (t < RROOM) { s_px[t] = pos[(n*RROOM+t)*2]; s_py[t] = pos[(n*RROOM+t)*2+1]; }
    if (t < RROOM*EMBD) s_emb[t] = emb[t];
    __syncthreads();
    for (int pix = t; pix < PIX; pix += blockDim.x) {
        int i = pix / MXY, j = pix % MXY;
        float acc[9];
        float em[EMBD];
        #pragma unroll
        for (int c = 0; c < 9; c++) acc[c] = 0.f;
        #pragma unroll
        for (int e = 0; e < EMBD; e++) em[e] = 0.f;
        #pragma unroll 1
        for (int r = 0; r < RROOM; r++) {
            int w = i - s_px[r], h = j - s_py[r];
            if ((unsigned)w < (unsigned)WW && (unsigned)h < (unsigned)HH) {
                const float* rp = rt + (r*9)*(WW*HH) + w*HH + h;
                float m0 = rp[0];
                #pragma unroll
                for (int c = 0; c < 9; c++) acc[c] += rp[c*(WW*HH)];
                #pragma unroll
                for (int e = 0; e < EMBD; e++) em[e] += s_emb[r*EMBD+e] * m0;
            }
        }
        float* xp = X0 + (size_t)n*CIN*PIX + pix;
        #pragma unroll
        for (int c = 0; c < 9; c++) xp[c*PIX] = acc[c];
        xp[9*PIX] = 1.0f;
        #pragma unroll
        for (int e = 0; e < EMBD; e++) xp[(10+e)*PIX] = em[e];
    }
}

// ---------------------------------------------------------------------------
// conv3x3 64->64, pad 1, ReLU  —  tf32 mma.sync, tap-major K ordering.
// K-chunk = 8 ic x 9 taps = 72; k = tap*8 + ic_local.
// In k8-step ks (=tap): b-pair rows (ks*8+tig, ks*8+tig+4) = (ic tig, ic tig+4),
// A cols likewise -> A addr = base + {0, 4*icstride} + const(di,dj). di/dj const
// per unrolled ks => zero per-step address ALU.
// ---------------------------------------------------------------------------
__global__ __launch_bounds__(288, 2)
void k_conv3_mma(const float* __restrict__ in, const float* __restrict__ w,
                 const float* __restrict__ bias, float* __restrict__ out) {
    int tile = blockIdx.x;           // 0..17 row-tile
    int n = blockIdx.y;
    int r0 = tile * 4;
    int t = threadIdx.x;
    int warp = t >> 5, lane = t & 31;
    int g = lane >> 2, tig = lane & 3;

    // ic stride = 6*76 = 456 words; 456 mod 32 = 8 -> tig bank octets disjoint
    __shared__ unsigned s_x[8][6][76];
    // packed B pairs: [ks][o][lane] = (k=ks*8+tig, k=ks*8+tig+4) for oc=o*8+g
    __shared__ uint2 s_wp[9][8][32];

    float acc[2][8][4];
    #pragma unroll
    for (int a = 0; a < 2; a++)
        #pragma unroll
        for (int o = 0; o < 8; o++)
            #pragma unroll
            for (int k = 0; k < 4; k++) acc[a][o][k] = 0.f;

    int prow[2][2], pcol[2][2];
    const unsigned* bptr[2][2];
    #pragma unroll
    for (int t2 = 0; t2 < 2; t2++)
        #pragma unroll
        for (int gi = 0; gi < 2; gi++) {
            int p = warp*32 + t2*16 + g + gi*8;   // 0..287
            prow[t2][gi] = p / 72;
            pcol[t2][gi] = p % 72;
            bptr[t2][gi] = &s_x[tig][prow[t2][gi]][pcol[t2][gi]];
        }

    const float* inb = in + (size_t)n * CMID * PIX;

    for (int c0 = 0; c0 < CMID; c0 += 8) {
        // --- input tile: 8 ic x 6 rows (halo 1) x 74 cols used ---
        for (int idx = t; idx < 8*6*74; idx += 288) {
            int c = idx / 444;
            int rem = idx % 444;
            int rr = rem / 74;
            int cidx = rem % 74;
            int cc = cidx - 1;
            int gi2 = r0 + rr - 1;
            float v = 0.f;
            if (cc >= 0 && cc < 72 && gi2 >= 0 && gi2 < 72)
                v = inb[(size_t)(c0 + c) * PIX + gi2*72 + cc];
            s_x[c][rr][cidx] = f2tf32(v);
        }
        // --- weights: k = tap*8 + icl ---
        for (int idx = t; idx < 9*8*32; idx += 288) {
            int ks = idx >> 8;
            int rem = idx & 255;
            int o = rem >> 5, l = rem & 31;
            int gg = l >> 2, tt = l & 3;
            int oc = o*8 + gg;
            uint2 pv;
            pv.x = f2tf32(w[oc*576 + (c0 + tt)*9 + ks]);
            pv.y = f2tf32(w[oc*576 + (c0 + tt + 4)*9 + ks]);
            s_wp[ks][o][l] = pv;
        }
        __syncthreads();

        #pragma unroll
        for (int ks = 0; ks < 9; ks++) {
            const int di = ks / 3, dj = ks % 3;
            const int off = di*76 + dj;
            unsigned av[2][4];
            #pragma unroll
            for (int t2 = 0; t2 < 2; t2++)
                #pragma unroll
                for (int gi = 0; gi < 2; gi++) {
                    av[t2][gi]     = bptr[t2][gi][off];           // icl = tig
                    av[t2][2 + gi] = bptr[t2][gi][4*456 + off];   // icl = tig+4
                }
            #pragma unroll
            for (int o = 0; o < 8; o++) {
                uint2 b = s_wp[ks][o][lane];
                mma_tf32(acc[0][o], av[0], b.x, b.y);
                mma_tf32(acc[1][o], av[1], b.x, b.y);
            }
        }
        __syncthreads();
    }

    float* outb = out + (size_t)n * CMID * PIX;
    #pragma unroll
    for (int o = 0; o < 8; o++) {
        int oc0 = o*8 + 2*tig;
        float bv0 = bias[oc0], bv1 = bias[oc0 + 1];
        #pragma unroll
        for (int t2 = 0; t2 < 2; t2++) {
            #pragma unroll
            for (int gi = 0; gi < 2; gi++) {
                int gr = r0 + prow[t2][gi];
                int gc = pcol[t2][gi];
                float v0 = acc[t2][o][gi*2 + 0] + bv0;
                float v1 = acc[t2][o][gi*2 + 1] + bv1;
                outb[(size_t)oc0 * PIX + gr*72 + gc]     = v0 > 0.f ? v0 : 0.f;
                outb[(size_t)(oc0+1) * PIX + gr*72 + gc] = v1 > 0.f ? v1 : 0.f;
            }
        }
    }
}

// ---------------------------------------------------------------------------
// conv5x5 16->64, pad 2, ReLU  —  tap-major: k = tap*4 + icl (25 taps x 4 ic,
// padded to 104 = 13 k8-steps). In step ks: pair rows -> taps (2ks, 2ks+1),
// icl = tig for both. tap 25 is zero-padded in B (A clamped to tap 24).
// ---------------------------------------------------------------------------
__global__ __launch_bounds__(288, 2)
void k_conv5_mma(const float* __restrict__ in, const float* __restrict__ w,
                 const float* __restrict__ bias, float* __restrict__ out) {
    int tile = blockIdx.x;
    int n = blockIdx.y;
    int r0 = tile * 4;
    int t = threadIdx.x;
    int warp = t >> 5, lane = t & 31;
    int g = lane >> 2, tig = lane & 3;

    // ic stride = 8*77 = 616 words; 616 mod 32 = 8
    __shared__ unsigned s_x[4][8][77];
    __shared__ uint2 s_wp[13][8][32];

    float acc[2][8][4];
    #pragma unroll
    for (int a = 0; a < 2; a++)
        #pragma unroll
        for (int o = 0; o < 8; o++)
            #pragma unroll
            for (int k = 0; k < 4; k++) acc[a][o][k] = 0.f;

    int prow[2][2], pcol[2][2];
    const unsigned* bptr[2][2];
    #pragma unroll
    for (int t2 = 0; t2 < 2; t2++)
        #pragma unroll
        for (int gi = 0; gi < 2; gi++) {
            int p = warp*32 + t2*16 + g + gi*8;
            prow[t2][gi] = p / 72;
            pcol[t2][gi] = p % 72;
            bptr[t2][gi] = &s_x[tig][prow[t2][gi]][pcol[t2][gi]];
        }

    const float* inb = in + (size_t)n * CIN * PIX;

    for (int c0 = 0; c0 < CIN; c0 += 4) {
        for (int idx = t; idx < 4*8*76; idx += 288) {
            int c = idx / 608;
            int rem = idx % 608;
            int rr = rem / 76;
            int cidx = rem % 76;
            int cc = cidx - 2;
            int gi2 = r0 + rr - 2;
            float v = 0.f;
            if (cc >= 0 && cc < 72 && gi2 >= 0 && gi2 < 72)
                v = inb[(size_t)(c0 + c) * PIX + gi2*72 + cc];
            s_x[c][rr][cidx] = f2tf32(v);
        }
        for (int idx = t; idx < 13*8*32; idx += 288) {
            int ks = idx >> 8;
            int rem = idx & 255;
            int o = rem >> 5, l = rem & 31;
            int gg = l >> 2, tt = l & 3;
            int oc = o*8 + gg;
            int tapA = 2*ks, tapB = 2*ks + 1;
            uint2 pv;
            pv.x = f2tf32(w[oc*400 + (c0 + tt)*25 + tapA]);
            pv.y = (tapB < 25) ? f2tf32(w[oc*400 + (c0 + tt)*25 + tapB]) : 0u;
            s_wp[ks][o][l] = pv;
        }
        __syncthreads();

        #pragma unroll
        for (int ks = 0; ks < 13; ks++) {
            const int tap0 = 2*ks;
            const int tap1 = (2*ks + 1 < 25) ? (2*ks + 1) : 24;  // B row zero at pad
            const int off0 = (tap0/5)*77 + (tap0%5);
            const int off1 = (tap1/5)*77 + (tap1%5);
            unsigned av[2][4];
            #pragma unroll
            for (int t2 = 0; t2 < 2; t2++)
                #pragma unroll
                for (int gi = 0; gi < 2; gi++) {
                    av[t2][gi]     = bptr[t2][gi][off0];
                    av[t2][2 + gi] = bptr[t2][gi][off1];
                }
            #pragma unroll
            for (int o = 0; o < 8; o++) {
                uint2 b = s_wp[ks][o][lane];
                mma_tf32(acc[0][o], av[0], b.x, b.y);
                mma_tf32(acc[1][o], av[1], b.x, b.y);
            }
        }
        __syncthreads();
    }

    float* outb = out + (size_t)n * CMID * PIX;
    #pragma unroll
    for (int o = 0; o < 8; o++) {
        int oc0 = o*8 + 2*tig;
        float bv0 = bias[oc0], bv1 = bias[oc0 + 1];
        #pragma unroll
        for (int t2 = 0; t2 < 2; t2++) {
            #pragma unroll
            for (int gi = 0; gi < 2; gi++) {
                int gr = r0 + prow[t2][gi];
                int gc = pcol[t2][gi];
                float v0 = acc[t2][o][gi*2 + 0] + bv0;
                float v1 = acc[t2][o][gi*2 + 1] + bv1;
                outb[(size_t)oc0 * PIX + gr*72 + gc]     = v0 > 0.f ? v0 : 0.f;
                outb[(size_t)(oc0+1) * PIX + gr*72 + gc] = v1 > 0.f ? v1 : 0.f;
            }
        }
    }
}

// ---------------------------------------------------------------------------
// Per-room window pooling
// ---------------------------------------------------------------------------
__global__ void k_feat(const float* __restrict__ X, const float* __restrict__ rt,
                       const int* __restrict__ pos, float* __restrict__ feat) {
    int b = blockIdx.x;            // n*32 + r
    int n = b >> 5, r = b & 31;
    int c = threadIdx.x;           // 0..63
    __shared__ float s_rm[48];
    if (c < 48) s_rm[c] = rt[r*9*48 + c];   // channel 0 = room_map
    __syncthreads();
    float rsum = 0.f;
    #pragma unroll
    for (int k = 0; k < 48; k++) rsum += s_rm[k];
    int px = pos[b*2], py = pos[b*2+1];
    const float* xp = X + (((size_t)n*CMID + c)*72 + px)*72 + py;
    float acc = 0.f;
    #pragma unroll
    for (int w = 0; w < WW; w++)
        #pragma unroll
        for (int h = 0; h < HH; h++)
            acc += s_rm[w*HH + h] * xp[w*72 + h];
    feat[b*64 + c] = acc / rsum;
}

// ---------------------------------------------------------------------------
// Per-room MLP 64->128->128 (ReLU), summed over rooms. 4 rooms per pass to
// amortize (transposed, coalesced) weight reads.
// ---------------------------------------------------------------------------
__global__ __launch_bounds__(128)
void k_room(const float* __restrict__ feat, const float* __restrict__ wt,
            const float* __restrict__ b1, const float* __restrict__ b2,
            float* __restrict__ S) {
    const float* w1t = wt;          // [64][128]
    const float* w2t = wt + 8192;   // [128][128]
    int n = blockIdx.x;
    int o = threadIdx.x;
    __shared__ float s_f[4][64];
    __shared__ float s_h1[4][128];
    float accS = 0.f;
    float bb1 = b1[o], bb2 = b2[o];
    for (int rg = 0; rg < 8; rg++) {
        #pragma unroll
        for (int i = o; i < 256; i += 128) {
            int r = i >> 6, c = i & 63;
            s_f[r][c] = feat[(n*RROOM + rg*4 + r)*64 + c];
        }
        __syncthreads();
        float a0 = bb1, a1 = bb1, a2 = bb1, a3 = bb1;
        #pragma unroll
        for (int c = 0; c < 64; c++) {
            float wv = w1t[c*128 + o];
            a0 += wv * s_f[0][c]; a1 += wv * s_f[1][c];
            a2 += wv * s_f[2][c]; a3 += wv * s_f[3][c];
        }
        s_h1[0][o] = fmaxf(a0, 0.f); s_h1[1][o] = fmaxf(a1, 0.f);
        s_h1[2][o] = fmaxf(a2, 0.f); s_h1[3][o] = fmaxf(a3, 0.f);
        __syncthreads();
        float z0 = bb2, z1 = bb2, z2 = bb2, z3 = bb2;
        #pragma unroll
        for (int c = 0; c < 128; c++) {
            float wv = w2t[c*128 + o];
            z0 += wv * s_h1[0][c]; z1 += wv * s_h1[1][c];
            z2 += wv * s_h1[2][c]; z3 += wv * s_h1[3][c];
        }
        accS += fmaxf(z0, 0.f) + fmaxf(z1, 0.f) + fmaxf(z2, 0.f) + fmaxf(z3, 0.f);
        __syncthreads();
    }
    S[n*128 + o] = accS;
}

// ---------------------------------------------------------------------------
// FC head: 128->256 ReLU -> 256->256. 4 images per block.
// ---------------------------------------------------------------------------
__global__ __launch_bounds__(256)
void k_fc(const float* __restrict__ S, const float* __restrict__ wt,
          const float* __restrict__ bf1, const float* __restrict__ bf2,
          float* __restrict__ out) {
    const float* wf1t = wt + 24576;  // [128][256]
    const float* wf2t = wt + 57344;  // [256][256]
    int n0 = blockIdx.x * 4;
    int o = threadIdx.x;
    __shared__ float s_in[4][128];
    __shared__ float s_h[4][256];
    #pragma unroll
    for (int i = o; i < 512; i += 256) {
        int q = i >> 7, c = i & 127;
        s_in[q][c] = S[(n0 + q)*128 + c];
    }
    __syncthreads();
    float a0 = bf1[o], a1 = a0, a2 = a0, a3 = a0;
    #pragma unroll
    for (int c = 0; c < 128; c++) {
        float wv = wf1t[c*256 + o];
        a0 += wv * s_in[0][c]; a1 += wv * s_in[1][c];
        a2 += wv * s_in[2][c]; a3 += wv * s_in[3][c];
    }
    s_h[0][o] = fmaxf(a0, 0.f); s_h[1][o] = fmaxf(a1, 0.f);
    s_h[2][o] = fmaxf(a2, 0.f); s_h[3][o] = fmaxf(a3, 0.f);
    __syncthreads();
    float z0 = bf2[o], z1 = z0, z2 = z0, z3 = z0;
    #pragma unroll
    for (int c = 0; c < 256; c++) {
        float wv = wf2t[c*256 + o];
        z0 += wv * s_h[0][c]; z1 += wv * s_h[1][c];
        z2 += wv * s_h[2][c]; z3 += wv * s_h[3][c];
    }
    out[(n0 + 0)*256 + o] = z0;
    out[(n0 + 1)*256 + o] = z1;
    out[(n0 + 2)*256 + o] = z2;
    out[(n0 + 3)*256 + o] = z3;
}

extern "C" void kernel_launch(void* const* d_in, const int* in_sizes, int n_in,
                              void* d_out, int out_size) {
    const int*   pos = (const int*)d_in[0];
    const float* rt  = (const float*)d_in[1];
    const float* emb = (const float*)d_in[2];
    const float* w1  = (const float*)d_in[3];
    const float* b1  = (const float*)d_in[4];
    const float* w2  = (const float*)d_in[5];
    const float* b2  = (const float*)d_in[6];
    const float* w3  = (const float*)d_in[7];
    const float* b3  = (const float*)d_in[8];
    const float* wr1 = (const float*)d_in[9];
    const float* br1 = (const float*)d_in[10];
    const float* wr2 = (const float*)d_in[11];
    const float* br2 = (const float*)d_in[12];
    const float* wf1 = (const float*)d_in[13];
    const float* bf1 = (const float*)d_in[14];
    const float* wf2 = (const float*)d_in[15];
    const float* bf2 = (const float*)d_in[16];
    float* out = (float*)d_out;

    float *X0, *XA, *XB, *feat, *S, *wt;
    cudaGetSymbolAddress((void**)&X0, g_X0);
    cudaGetSymbolAddress((void**)&XA, g_XA);
    cudaGetSymbolAddress((void**)&XB, g_XB);
    cudaGetSymbolAddress((void**)&feat, g_feat);
    cudaGetSymbolAddress((void**)&S, g_S);
    cudaGetSymbolAddress((void**)&wt, g_wt);

    k_prep<<<64, 256>>>(wr1, wr2, wf1, wf2, wt);
    k_build<<<NIMG, 256>>>(pos, rt, emb, X0);
    k_conv5_mma<<<dim3(18, NIMG), 288>>>(X0, w1, b1, XA);
    k_conv3_mma<<<dim3(18, NIMG), 288>>>(XA, w2, b2, XB);
    k_conv3_mma<<<dim3(18, NIMG), 288>>>(XB, w3, b3, XA);
    k_feat<<<NIMG*RROOM, 64>>>(XA, rt, pos, feat);
    k_room<<<NIMG, 128>>>(feat, wt, br1, br2, S);
    k_fc<<<NIMG/4, 256>>>(S, wt, bf1, bf2, out);
}

// round 4
// speedup vs baseline: 4.6343x; 1.3669x over previous
#include <cuda_runtime.h>

// Problem constants
#define NIMG 256
#define RROOM 32
#define WW 8
#define HH 6
#define MXY 72
#define PIX (MXY*MXY)
#define EMBD 6
#define CIN 16
#define CMID 64

// Scratch (device globals; no allocation allowed)
__device__ float g_X0[NIMG*CIN*PIX];    // 21.2 MB (tf32-rounded bits)
__device__ float g_XA[NIMG*CMID*PIX];   // 84.9 MB
__device__ float g_XB[NIMG*CMID*PIX];   // 84.9 MB
__device__ float g_feat[NIMG*RROOM*64]; // 2 MB
__device__ float g_S[NIMG*128];
__device__ float g_wt[122880];          // transposed FC weights
// packed conv weights (mma-ready, tf32): conv5 @0 (13312), conv3A @13312 (18432), conv3B @31744 (18432)
__device__ uint2 g_wp[50176];

// ---------------------------------------------------------------------------
// helpers
// ---------------------------------------------------------------------------
__device__ __forceinline__ unsigned f2tf32(float x) {
    unsigned u;
    asm("cvt.rna.tf32.f32 %0, %1;" : "=r"(u) : "f"(x));
    return u;
}

__device__ __forceinline__ void mma_tf32(float d[4], const unsigned a[4],
                                         unsigned b0, unsigned b1) {
    asm volatile(
        "mma.sync.aligned.m16n8k8.row.col.f32.tf32.tf32.f32 "
        "{%0,%1,%2,%3},{%4,%5,%6,%7},{%8,%9},{%0,%1,%2,%3};"
        : "+f"(d[0]), "+f"(d[1]), "+f"(d[2]), "+f"(d[3])
        : "r"(a[0]), "r"(a[1]), "r"(a[2]), "r"(a[3]), "r"(b0), "r"(b1));
}

// ---------------------------------------------------------------------------
// one-shot prep: FC weight transposes + conv weight packing (tf32, mma layout)
// ---------------------------------------------------------------------------
__global__ void k_prep(const float* __restrict__ w1, const float* __restrict__ w2,
                       const float* __restrict__ w3,
                       const float* __restrict__ wr1, const float* __restrict__ wr2,
                       const float* __restrict__ wf1, const float* __restrict__ wf2,
                       float* __restrict__ wt, uint2* __restrict__ wp) {
    int t0 = blockIdx.x * blockDim.x + threadIdx.x;
    int stride = gridDim.x * blockDim.x;
    for (int i = t0; i < 8192; i += stride)  { int c = i >> 7, o = i & 127; wt[i]         = wr1[o*64 + c]; }
    for (int i = t0; i < 16384; i += stride) { int c = i >> 7, o = i & 127; wt[8192 + i]  = wr2[o*128 + c]; }
    for (int i = t0; i < 32768; i += stride) { int c = i >> 8, o = i & 255; wt[24576 + i] = wf1[o*128 + c]; }
    for (int i = t0; i < 65536; i += stride) { int c = i >> 8, o = i & 255; wt[57344 + i] = wf2[o*256 + c]; }
    // conv5 pack: [cc(4)][ks(13)][o(8)][lane(32)]
    for (int i = t0; i < 13312; i += stride) {
        int lane = i & 31, rest = i >> 5;
        int o = rest & 7; rest >>= 3;
        int ks = rest % 13, cc = rest / 13;
        int gg = lane >> 2, tt = lane & 3;
        int oc = o*8 + gg, c0 = cc*4;
        int tapA = 2*ks, tapB = 2*ks + 1;
        uint2 pv;
        pv.x = f2tf32(w1[oc*400 + (c0 + tt)*25 + tapA]);
        pv.y = (tapB < 25) ? f2tf32(w1[oc*400 + (c0 + tt)*25 + tapB]) : 0u;
        wp[i] = pv;
    }
    // conv3 packs: [cc(8)][ks(9)][o(8)][lane(32)]
    for (int i = t0; i < 18432; i += stride) {
        int lane = i & 31, rest = i >> 5;
        int o = rest & 7; rest >>= 3;
        int ks = rest % 9, cc = rest / 9;
        int gg = lane >> 2, tt = lane & 3;
        int oc = o*8 + gg, ic = cc*8 + tt;
        uint2 pv, qv;
        pv.x = f2tf32(w2[oc*576 + ic*9 + ks]);
        pv.y = f2tf32(w2[oc*576 + (ic+4)*9 + ks]);
        wp[13312 + i] = pv;
        qv.x = f2tf32(w3[oc*576 + ic*9 + ks]);
        qv.y = f2tf32(w3[oc*576 + (ic+4)*9 + ks]);
        wp[31744 + i] = qv;
    }
}

// ---------------------------------------------------------------------------
// Stage 1: build input X0 (tf32-rounded) by GATHER over rooms. grid (4, NIMG).
// ---------------------------------------------------------------------------
__global__ void k_build(const int* __restrict__ pos, const float* __restrict__ rt,
                        const float* __restrict__ emb, float* __restrict__ X0) {
    int n = blockIdx.y;
    int q = blockIdx.x;
    __shared__ int s_px[RROOM], s_py[RROOM];
    __shared__ float s_emb[RROOM*EMBD];
    int t = threadIdx.x;
    if (t < RROOM) { s_px[t] = pos[(n*RROOM+t)*2]; s_py[t] = pos[(n*RROOM+t)*2+1]; }
    if (t < RROOM*EMBD) s_emb[t] = emb[t];
    __syncthreads();
    int p0 = q * 1296, p1 = p0 + 1296;
    for (int pix = p0 + t; pix < p1; pix += blockDim.x) {
        int i = pix / MXY, j = pix % MXY;
        float acc[9];
        float em[EMBD];
        #pragma unroll
        for (int c = 0; c < 9; c++) acc[c] = 0.f;
        #pragma unroll
        for (int e = 0; e < EMBD; e++) em[e] = 0.f;
        #pragma unroll 1
        for (int r = 0; r < RROOM; r++) {
            int w = i - s_px[r], h = j - s_py[r];
            if ((unsigned)w < (unsigned)WW && (unsigned)h < (unsigned)HH) {
                const float* rp = rt + (r*9)*(WW*HH) + w*HH + h;
                float m0 = rp[0];
                #pragma unroll
                for (int c = 0; c < 9; c++) acc[c] += rp[c*(WW*HH)];
                #pragma unroll
                for (int e = 0; e < EMBD; e++) em[e] += s_emb[r*EMBD+e] * m0;
            }
        }
        float* xp = X0 + (size_t)n*CIN*PIX + pix;
        #pragma unroll
        for (int c = 0; c < 9; c++) xp[c*PIX] = __uint_as_float(f2tf32(acc[c]));
        xp[9*PIX] = 1.0f;
        #pragma unroll
        for (int e = 0; e < EMBD; e++) xp[(10+e)*PIX] = __uint_as_float(f2tf32(em[e]));
    }
}

// ---------------------------------------------------------------------------
// conv3x3 64->64, pad 1, ReLU. tf32 mma, tap-major K, software pipelined:
// chunk c+1 input+weights prefetched into regs during compute of chunk c.
// Weights come pre-packed/pre-converted from g_wp -> loader is a flat copy.
// ---------------------------------------------------------------------------
__global__ __launch_bounds__(288, 2)
void k_conv3_mma(const float* __restrict__ in, const uint2* __restrict__ wp,
                 const float* __restrict__ bias, float* __restrict__ out) {
    int tile = blockIdx.x;           // 0..17 row-tile
    int n = blockIdx.y;
    int r0 = tile * 4;
    int t = threadIdx.x;
    int warp = t >> 5, lane = t & 31;
    int g = lane >> 2, tig = lane & 3;

    __shared__ unsigned s_x[8][6][76];   // ic stride 456 words (456%32==8)
    __shared__ uint2 s_wf[2304];         // [ks][o][lane]

    float acc[2][8][4];
    #pragma unroll
    for (int a = 0; a < 2; a++)
        #pragma unroll
        for (int o = 0; o < 8; o++)
            #pragma unroll
            for (int k = 0; k < 4; k++) acc[a][o][k] = 0.f;

    int prow[2][2], pcol[2][2];
    unsigned axoff[2][2];
    #pragma unroll
    for (int t2 = 0; t2 < 2; t2++)
        #pragma unroll
        for (int gi = 0; gi < 2; gi++) {
            int p = warp*32 + t2*16 + g + gi*8;   // 0..287
            prow[t2][gi] = p / 72;
            pcol[t2][gi] = p % 72;
            axoff[t2][gi] = tig*456 + prow[t2][gi]*76 + pcol[t2][gi];
        }
    const unsigned* sx = &s_x[0][0][0];

    const float* inb = in + (size_t)n * CMID * PIX;

    // hoisted input-loader tuples (2 per thread; 444 total slots)
    int li_rr[2], li_cx[2];
    const float* li_p[2];
    bool li_v[2], li_a[2];
    #pragma unroll
    for (int q2 = 0; q2 < 2; q2++) {
        int idx = t + q2*288;
        li_a[q2] = idx < 444;
        int rr = idx / 74, cx = idx % 74;
        int cc2 = cx - 1, gi2 = r0 + rr - 1;
        li_rr[q2] = rr; li_cx[q2] = cx;
        li_v[q2] = li_a[q2] && cc2 >= 0 && cc2 < 72 && gi2 >= 0 && gi2 < 72;
        li_p[q2] = li_v[q2] ? (inb + gi2*72 + cc2) : inb;
    }

    float pinv[2][8];
    uint2 pw[8];

    // ---- prologue: fetch chunk 0 into regs, publish to smem ----
    #pragma unroll
    for (int j = 0; j < 8; j++) pw[j] = wp[t + j*288];
    #pragma unroll
    for (int q2 = 0; q2 < 2; q2++)
        #pragma unroll
        for (int c = 0; c < 8; c++)
            pinv[q2][c] = li_v[q2] ? __ldg(li_p[q2] + (size_t)c * PIX) : 0.f;
    #pragma unroll
    for (int j = 0; j < 8; j++) s_wf[t + j*288] = pw[j];
    #pragma unroll
    for (int q2 = 0; q2 < 2; q2++)
        if (li_a[q2]) {
            #pragma unroll
            for (int c = 0; c < 8; c++)
                s_x[c][li_rr[q2]][li_cx[q2]] = __float_as_uint(pinv[q2][c]);
        }
    __syncthreads();

    for (int cc = 0; cc < 8; cc++) {
        bool more = cc < 7;
        if (more) {
            const uint2* wpn = wp + (cc+1)*2304;
            #pragma unroll
            for (int j = 0; j < 8; j++) pw[j] = wpn[t + j*288];
            int c0 = (cc+1)*8;
            #pragma unroll
            for (int q2 = 0; q2 < 2; q2++)
                #pragma unroll
                for (int c = 0; c < 8; c++)
                    pinv[q2][c] = li_v[q2] ? __ldg(li_p[q2] + (size_t)(c0+c) * PIX) : 0.f;
        }
        // ---- compute chunk cc ----
        #pragma unroll
        for (int ks = 0; ks < 9; ks++) {
            const int off = (ks/3)*76 + (ks%3);
            unsigned av[2][4];
            #pragma unroll
            for (int t2 = 0; t2 < 2; t2++)
                #pragma unroll
                for (int gi = 0; gi < 2; gi++) {
                    av[t2][gi]     = sx[axoff[t2][gi] + off];
                    av[t2][2 + gi] = sx[axoff[t2][gi] + 4*456 + off];
                }
            #pragma unroll
            for (int o = 0; o < 8; o++) {
                uint2 b = s_wf[ks*256 + o*32 + lane];
                mma_tf32(acc[0][o], av[0], b.x, b.y);
                mma_tf32(acc[1][o], av[1], b.x, b.y);
            }
        }
        __syncthreads();
        if (more) {
            #pragma unroll
            for (int j = 0; j < 8; j++) s_wf[t + j*288] = pw[j];
            #pragma unroll
            for (int q2 = 0; q2 < 2; q2++)
                if (li_a[q2]) {
                    #pragma unroll
                    for (int c = 0; c < 8; c++)
                        s_x[c][li_rr[q2]][li_cx[q2]] = __float_as_uint(pinv[q2][c]);
                }
            __syncthreads();
        }
    }

    // ---- epilogue: bias + ReLU + tf32 round, NCHW store ----
    float* outb = out + (size_t)n * CMID * PIX;
    #pragma unroll
    for (int o = 0; o < 8; o++) {
        int oc0 = o*8 + 2*tig;
        float bv0 = bias[oc0], bv1 = bias[oc0 + 1];
        #pragma unroll
        for (int t2 = 0; t2 < 2; t2++) {
            #pragma unroll
            for (int gi = 0; gi < 2; gi++) {
                int gr = r0 + prow[t2][gi];
                int gc = pcol[t2][gi];
                float v0 = fmaxf(acc[t2][o][gi*2 + 0] + bv0, 0.f);
                float v1 = fmaxf(acc[t2][o][gi*2 + 1] + bv1, 0.f);
                outb[(size_t)oc0 * PIX + gr*72 + gc]     = __uint_as_float(f2tf32(v0));
                outb[(size_t)(oc0+1) * PIX + gr*72 + gc] = __uint_as_float(f2tf32(v1));
            }
        }
    }
}

// ---------------------------------------------------------------------------
// conv5x5 16->64, pad 2, ReLU. tap-major; input reg-prefetched, weights
// copied flat from pack (4 chunks only).
// ---------------------------------------------------------------------------
__global__ __launch_bounds__(288, 2)
void k_conv5_mma(const float* __restrict__ in, const uint2* __restrict__ wp,
                 const float* __restrict__ bias, float* __restrict__ out) {
    int tile = blockIdx.x;
    int n = blockIdx.y;
    int r0 = tile * 4;
    int t = threadIdx.x;
    int warp = t >> 5, lane = t & 31;
    int g = lane >> 2, tig = lane & 3;

    __shared__ unsigned s_x[4][8][77];   // ic stride 616 (616%32==8)
    __shared__ uint2 s_wf[3328];         // [ks(13)][o][lane]

    float acc[2][8][4];
    #pragma unroll
    for (int a = 0; a < 2; a++)
        #pragma unroll
        for (int o = 0; o < 8; o++)
            #pragma unroll
            for (int k = 0; k < 4; k++) acc[a][o][k] = 0.f;

    int prow[2][2], pcol[2][2];
    unsigned axoff[2][2];
    #pragma unroll
    for (int t2 = 0; t2 < 2; t2++)
        #pragma unroll
        for (int gi = 0; gi < 2; gi++) {
            int p = warp*32 + t2*16 + g + gi*8;
            prow[t2][gi] = p / 72;
            pcol[t2][gi] = p % 72;
            axoff[t2][gi] = tig*616 + prow[t2][gi]*77 + pcol[t2][gi];
        }
    const unsigned* sx = &s_x[0][0][0];

    const float* inb = in + (size_t)n * CIN * PIX;

    // loader tuples: 608 slots = 8 rows x 76 cols; 3 per thread
    int li_rr[3], li_cx[3];
    const float* li_p[3];
    bool li_v[3], li_a[3];
    #pragma unroll
    for (int q2 = 0; q2 < 3; q2++) {
        int idx = t + q2*288;
        li_a[q2] = idx < 608;
        int rr = idx / 76, cx = idx % 76;
        int cc2 = cx - 2, gi2 = r0 + rr - 2;
        li_rr[q2] = rr; li_cx[q2] = cx;
        li_v[q2] = li_a[q2] && cc2 >= 0 && cc2 < 72 && gi2 >= 0 && gi2 < 72;
        li_p[q2] = li_v[q2] ? (inb + gi2*72 + cc2) : inb;
    }

    float pinv[3][4];

    // prologue: input chunk 0 regs; weights chunk 0 direct
    #pragma unroll
    for (int q2 = 0; q2 < 3; q2++)
        #pragma unroll
        for (int c = 0; c < 4; c++)
            pinv[q2][c] = li_v[q2] ? __ldg(li_p[q2] + (size_t)c * PIX) : 0.f;
    #pragma unroll
    for (int j = 0; j < 12; j++) {
        int idx = t + j*288;
        if (idx < 3328) s_wf[idx] = wp[idx];
    }
    #pragma unroll
    for (int q2 = 0; q2 < 3; q2++)
        if (li_a[q2]) {
            #pragma unroll
            for (int c = 0; c < 4; c++)
                s_x[c][li_rr[q2]][li_cx[q2]] = __float_as_uint(pinv[q2][c]);
        }
    __syncthreads();

    for (int cc = 0; cc < 4; cc++) {
        bool more = cc < 3;
        if (more) {
            int c0 = (cc+1)*4;
            #pragma unroll
            for (int q2 = 0; q2 < 3; q2++)
                #pragma unroll
                for (int c = 0; c < 4; c++)
                    pinv[q2][c] = li_v[q2] ? __ldg(li_p[q2] + (size_t)(c0+c) * PIX) : 0.f;
        }
        #pragma unroll
        for (int ks = 0; ks < 13; ks++) {
            const int tap0 = 2*ks;
            const int tap1 = (2*ks + 1 < 25) ? (2*ks + 1) : 24;
            const int off0 = (tap0/5)*77 + (tap0%5);
            const int off1 = (tap1/5)*77 + (tap1%5);
            unsigned av[2][4];
            #pragma unroll
            for (int t2 = 0; t2 < 2; t2++)
                #pragma unroll
                for (int gi = 0; gi < 2; gi++) {
                    av[t2][gi]     = sx[axoff[t2][gi] + off0];
                    av[t2][2 + gi] = sx[axoff[t2][gi] + off1];
                }
            #pragma unroll
            for (int o = 0; o < 8; o++) {
                uint2 b = s_wf[ks*256 + o*32 + lane];
                mma_tf32(acc[0][o], av[0], b.x, b.y);
                mma_tf32(acc[1][o], av[1], b.x, b.y);
            }
        }
        __syncthreads();
        if (more) {
            const uint2* wpn = wp + (cc+1)*3328;
            #pragma unroll
            for (int j = 0; j < 12; j++) {
                int idx = t + j*288;
                if (idx < 3328) s_wf[idx] = wpn[idx];
            }
            #pragma unroll
            for (int q2 = 0; q2 < 3; q2++)
                if (li_a[q2]) {
                    #pragma unroll
                    for (int c = 0; c < 4; c++)
                        s_x[c][li_rr[q2]][li_cx[q2]] = __float_as_uint(pinv[q2][c]);
                }
            __syncthreads();
        }
    }

    float* outb = out + (size_t)n * CMID * PIX;
    #pragma unroll
    for (int o = 0; o < 8; o++) {
        int oc0 = o*8 + 2*tig;
        float bv0 = bias[oc0], bv1 = bias[oc0 + 1];
        #pragma unroll
        for (int t2 = 0; t2 < 2; t2++) {
            #pragma unroll
            for (int gi = 0; gi < 2; gi++) {
                int gr = r0 + prow[t2][gi];
                int gc = pcol[t2][gi];
                float v0 = fmaxf(acc[t2][o][gi*2 + 0] + bv0, 0.f);
                float v1 = fmaxf(acc[t2][o][gi*2 + 1] + bv1, 0.f);
                outb[(size_t)oc0 * PIX + gr*72 + gc]     = __uint_as_float(f2tf32(v0));
                outb[(size_t)(oc0+1) * PIX + gr*72 + gc] = __uint_as_float(f2tf32(v1));
            }
        }
    }
}

// ---------------------------------------------------------------------------
// Per-room window pooling
// ---------------------------------------------------------------------------
__global__ void k_feat(const float* __restrict__ X, const float* __restrict__ rt,
                       const int* __restrict__ pos, float* __restrict__ feat) {
    int b = blockIdx.x;            // n*32 + r
    int n = b >> 5, r = b & 31;
    int c = threadIdx.x;           // 0..63
    __shared__ float s_rm[48];
    if (c < 48) s_rm[c] = rt[r*9*48 + c];   // channel 0 = room_map
    __syncthreads();
    float rsum = 0.f;
    #pragma unroll
    for (int k = 0; k < 48; k++) rsum += s_rm[k];
    int px = pos[b*2], py = pos[b*2+1];
    const float* xp = X + (((size_t)n*CMID + c)*72 + px)*72 + py;
    float acc = 0.f;
    #pragma unroll
    for (int w = 0; w < WW; w++)
        #pragma unroll
        for (int h = 0; h < HH; h++)
            acc += s_rm[w*HH + h] * xp[w*72 + h];
    feat[b*64 + c] = acc / rsum;
}

// ---------------------------------------------------------------------------
// Per-room MLP 64->128->128 (ReLU), summed over rooms. 4 rooms per pass.
// ---------------------------------------------------------------------------
__global__ __launch_bounds__(128)
void k_room(const float* __restrict__ feat, const float* __restrict__ wt,
            const float* __restrict__ b1, const float* __restrict__ b2,
            float* __restrict__ S) {
    const float* w1t = wt;          // [64][128]
    const float* w2t = wt + 8192;   // [128][128]
    int n = blockIdx.x;
    int o = threadIdx.x;
    __shared__ float s_f[4][64];
    __shared__ float s_h1[4][128];
    float accS = 0.f;
    float bb1 = b1[o], bb2 = b2[o];
    for (int rg = 0; rg < 8; rg++) {
        #pragma unroll
        for (int i = o; i < 256; i += 128) {
            int r = i >> 6, c = i & 63;
            s_f[r][c] = feat[(n*RROOM + rg*4 + r)*64 + c];
        }
        __syncthreads();
        float a0 = bb1, a1 = bb1, a2 = bb1, a3 = bb1;
        #pragma unroll
        for (int c = 0; c < 64; c++) {
            float wv = w1t[c*128 + o];
            a0 += wv * s_f[0][c]; a1 += wv * s_f[1][c];
            a2 += wv * s_f[2][c]; a3 += wv * s_f[3][c];
        }
        s_h1[0][o] = fmaxf(a0, 0.f); s_h1[1][o] = fmaxf(a1, 0.f);
        s_h1[2][o] = fmaxf(a2, 0.f); s_h1[3][o] = fmaxf(a3, 0.f);
        __syncthreads();
        float z0 = bb2, z1 = bb2, z2 = bb2, z3 = bb2;
        #pragma unroll
        for (int c = 0; c < 128; c++) {
            float wv = w2t[c*128 + o];
            z0 += wv * s_h1[0][c]; z1 += wv * s_h1[1][c];
            z2 += wv * s_h1[2][c]; z3 += wv * s_h1[3][c];
        }
        accS += fmaxf(z0, 0.f) + fmaxf(z1, 0.f) + fmaxf(z2, 0.f) + fmaxf(z3, 0.f);
        __syncthreads();
    }
    S[n*128 + o] = accS;
}

// ---------------------------------------------------------------------------
// FC head: 128->256 ReLU -> 256->256. 4 images per block.
// ---------------------------------------------------------------------------
__global__ __launch_bounds__(256)
void k_fc(const float* __restrict__ S, const float* __restrict__ wt,
          const float* __restrict__ bf1, const float* __restrict__ bf2,
          float* __restrict__ out) {
    const float* wf1t = wt + 24576;  // [128][256]
    const float* wf2t = wt + 57344;  // [256][256]
    int n0 = blockIdx.x * 4;
    int o = threadIdx.x;
    __shared__ float s_in[4][128];
    __shared__ float s_h[4][256];
    #pragma unroll
    for (int i = o; i < 512; i += 256) {
        int q = i >> 7, c = i & 127;
        s_in[q][c] = S[(n0 + q)*128 + c];
    }
    __syncthreads();
    float a0 = bf1[o], a1 = a0, a2 = a0, a3 = a0;
    #pragma unroll
    for (int c = 0; c < 128; c++) {
        float wv = wf1t[c*256 + o];
        a0 += wv * s_in[0][c]; a1 += wv * s_in[1][c];
        a2 += wv * s_in[2][c]; a3 += wv * s_in[3][c];
    }
    s_h[0][o] = fmaxf(a0, 0.f); s_h[1][o] = fmaxf(a1, 0.f);
    s_h[2][o] = fmaxf(a2, 0.f); s_h[3][o] = fmaxf(a3, 0.f);
    __syncthreads();
    float z0 = bf2[o], z1 = z0, z2 = z0, z3 = z0;
    #pragma unroll
    for (int c = 0; c < 256; c++) {
        float wv = wf2t[c*256 + o];
        z0 += wv * s_h[0][c]; z1 += wv * s_h[1][c];
        z2 += wv * s_h[2][c]; z3 += wv * s_h[3][c];
    }
    out[(n0 + 0)*256 + o] = z0;
    out[(n0 + 1)*256 + o] = z1;
    out[(n0 + 2)*256 + o] = z2;
    out[(n0 + 3)*256 + o] = z3;
}

extern "C" void kernel_launch(void* const* d_in, const int* in_sizes, int n_in,
                              void* d_out, int out_size) {
    const int*   pos = (const int*)d_in[0];
    const float* rt  = (const float*)d_in[1];
    const float* emb = (const float*)d_in[2];
    const float* w1  = (const float*)d_in[3];
    const float* b1  = (const float*)d_in[4];
    const float* w2  = (const float*)d_in[5];
    const float* b2  = (const float*)d_in[6];
    const float* w3  = (const float*)d_in[7];
    const float* b3  = (const float*)d_in[8];
    const float* wr1 = (const float*)d_in[9];
    const float* br1 = (const float*)d_in[10];
    const float* wr2 = (const float*)d_in[11];
    const float* br2 = (const float*)d_in[12];
    const float* wf1 = (const float*)d_in[13];
    const float* bf1 = (const float*)d_in[14];
    const float* wf2 = (const float*)d_in[15];
    const float* bf2 = (const float*)d_in[16];
    float* out = (float*)d_out;

    float *X0, *XA, *XB, *feat, *S, *wt;
    uint2 *wpk;
    cudaGetSymbolAddress((void**)&X0, g_X0);
    cudaGetSymbolAddress((void**)&XA, g_XA);
    cudaGetSymbolAddress((void**)&XB, g_XB);
    cudaGetSymbolAddress((void**)&feat, g_feat);
    cudaGetSymbolAddress((void**)&S, g_S);
    cudaGetSymbolAddress((void**)&wt, g_wt);
    cudaGetSymbolAddress((void**)&wpk, g_wp);

    k_prep<<<96, 256>>>(w1, w2, w3, wr1, wr2, wf1, wf2, wt, wpk);
    k_build<<<dim3(4, NIMG), 256>>>(pos, rt, emb, X0);
    k_conv5_mma<<<dim3(18, NIMG), 288>>>(X0, wpk, b1, XA);
    k_conv3_mma<<<dim3(18, NIMG), 288>>>(XA, wpk + 13312, b2, XB);
    k_conv3_mma<<<dim3(18, NIMG), 288>>>(XB, wpk + 31744, b3, XA);
    k_feat<<<NIMG*RROOM, 64>>>(XA, rt, pos, feat);
    k_room<<<NIMG, 128>>>(feat, wt, br1, br2, S);
    k_fc<<<NIMG/4, 256>>>(S, wt, bf1, bf2, out);
}

// round 5
// speedup vs baseline: 8.7054x; 1.8785x over previous
#include <cuda_runtime.h>
#include <cuda_fp16.h>

// Problem constants
#define NIMG 256
#define RROOM 32
#define WW 8
#define HH 6
#define MXY 72
#define PIX (MXY*MXY)
#define EMBD 6
#define CIN 16
#define CMID 64

// Scratch (device globals; no allocation allowed).
// Activations stored as channel-paired half2 (unsigned): [n][ch/2][PIX]
__device__ unsigned g_X0h[NIMG*8*PIX];    // 42.5 MB
__device__ unsigned g_XAh[NIMG*32*PIX];   // 170 MB
__device__ unsigned g_XBh[NIMG*32*PIX];   // 170 MB
__device__ float g_feat[NIMG*RROOM*64];
__device__ float g_S[NIMG*128];
__device__ float g_wt[122880];            // transposed FC weights
// packed fp16 conv weights: conv5 @0 (6656), conv3A @6656 (9216), conv3B @15872 (9216)
__device__ uint2 g_wp[25088];

// ---------------------------------------------------------------------------
// helpers
// ---------------------------------------------------------------------------
__device__ __forceinline__ unsigned f2h2(float lo, float hi) {
    __half2 h = __floats2half2_rn(lo, hi);
    return *reinterpret_cast<unsigned*>(&h);
}

__device__ __forceinline__ void mma_f16(float d[4], const unsigned a[4],
                                        unsigned b0, unsigned b1) {
    asm volatile(
        "mma.sync.aligned.m16n8k16.row.col.f32.f16.f16.f32 "
        "{%0,%1,%2,%3},{%4,%5,%6,%7},{%8,%9},{%0,%1,%2,%3};"
        : "+f"(d[0]), "+f"(d[1]), "+f"(d[2]), "+f"(d[3])
        : "r"(a[0]), "r"(a[1]), "r"(a[2]), "r"(a[3]), "r"(b0), "r"(b1));
}

// ---------------------------------------------------------------------------
// one-shot prep: FC transposes + fp16 conv weight packing (mma-ready)
// ---------------------------------------------------------------------------
__global__ void k_prep(const float* __restrict__ w1, const float* __restrict__ w2,
                       const float* __restrict__ w3,
                       const float* __restrict__ wr1, const float* __restrict__ wr2,
                       const float* __restrict__ wf1, const float* __restrict__ wf2,
                       float* __restrict__ wt, uint2* __restrict__ wp) {
    int t0 = blockIdx.x * blockDim.x + threadIdx.x;
    int stride = gridDim.x * blockDim.x;
    for (int i = t0; i < 8192; i += stride)  { int c = i >> 7, o = i & 127; wt[i]         = wr1[o*64 + c]; }
    for (int i = t0; i < 16384; i += stride) { int c = i >> 7, o = i & 127; wt[8192 + i]  = wr2[o*128 + c]; }
    for (int i = t0; i < 32768; i += stride) { int c = i >> 8, o = i & 255; wt[24576 + i] = wf1[o*128 + c]; }
    for (int i = t0; i < 65536; i += stride) { int c = i >> 8, o = i & 255; wt[57344 + i] = wf2[o*256 + c]; }
    // conv5 pack: [cc(2)][ks(13)][o(8)][lane(32)]. chunk = 8 ic; k16 = taps (2ks,2ks+1) x ic-pairs
    for (int i = t0; i < 6656; i += stride) {
        int lane = i & 31, rest = i >> 5;
        int o = rest & 7; rest >>= 3;
        int ks = rest % 13, cc = rest / 13;
        int gg = lane >> 2, tt = lane & 3;
        int oc = o*8 + gg;
        int ic0 = cc*8 + 2*tt;
        int tap0 = 2*ks, tap1 = 2*ks + 1;
        uint2 pv;
        pv.x = f2h2(w1[oc*400 + ic0*25 + tap0], w1[oc*400 + (ic0+1)*25 + tap0]);
        pv.y = (tap1 < 25) ? f2h2(w1[oc*400 + ic0*25 + tap1], w1[oc*400 + (ic0+1)*25 + tap1]) : 0u;
        wp[i] = pv;
    }
    // conv3 packs: [cc(4)][ks(9)][o(8)][lane(32)]. chunk = 16 ic; k16 = one tap x 16 ic
    for (int i = t0; i < 9216; i += stride) {
        int lane = i & 31, rest = i >> 5;
        int o = rest & 7; rest >>= 3;
        int ks = rest % 9, cc = rest / 9;
        int gg = lane >> 2, tt = lane & 3;
        int oc = o*8 + gg;
        int icA = cc*16 + 2*tt;        // k-pair (2tig, 2tig+1)
        int icB = cc*16 + 2*tt + 8;    // k-pair (2tig+8, 2tig+9)
        uint2 pv, qv;
        pv.x = f2h2(w2[oc*576 + icA*9 + ks], w2[oc*576 + (icA+1)*9 + ks]);
        pv.y = f2h2(w2[oc*576 + icB*9 + ks], w2[oc*576 + (icB+1)*9 + ks]);
        wp[6656 + i] = pv;
        qv.x = f2h2(w3[oc*576 + icA*9 + ks], w3[oc*576 + (icA+1)*9 + ks]);
        qv.y = f2h2(w3[oc*576 + icB*9 + ks], w3[oc*576 + (icB+1)*9 + ks]);
        wp[15872 + i] = qv;
    }
}

// ---------------------------------------------------------------------------
// Stage 1: build input X0 (fp16 channel-paired) by GATHER over rooms.
// ---------------------------------------------------------------------------
__global__ void k_build(const int* __restrict__ pos, const float* __restrict__ rt,
                        const float* __restrict__ emb, unsigned* __restrict__ X0h) {
    int n = blockIdx.y;
    int q = blockIdx.x;
    __shared__ int s_px[RROOM], s_py[RROOM];
    __shared__ float s_emb[RROOM*EMBD];
    int t = threadIdx.x;
    if (t < RROOM) { s_px[t] = pos[(n*RROOM+t)*2]; s_py[t] = pos[(n*RROOM+t)*2+1]; }
    if (t < RROOM*EMBD) s_emb[t] = emb[t];
    __syncthreads();
    int p0 = q * 1296, p1 = p0 + 1296;
    for (int pix = p0 + t; pix < p1; pix += blockDim.x) {
        int i = pix / MXY, j = pix % MXY;
        float acc[9];
        float em[EMBD];
        #pragma unroll
        for (int c = 0; c < 9; c++) acc[c] = 0.f;
        #pragma unroll
        for (int e = 0; e < EMBD; e++) em[e] = 0.f;
        #pragma unroll 1
        for (int r = 0; r < RROOM; r++) {
            int w = i - s_px[r], h = j - s_py[r];
            if ((unsigned)w < (unsigned)WW && (unsigned)h < (unsigned)HH) {
                const float* rp = rt + (r*9)*(WW*HH) + w*HH + h;
                float m0 = rp[0];
                #pragma unroll
                for (int c = 0; c < 9; c++) acc[c] += rp[c*(WW*HH)];
                #pragma unroll
                for (int e = 0; e < EMBD; e++) em[e] += s_emb[r*EMBD+e] * m0;
            }
        }
        unsigned* xp = X0h + (size_t)n*8*PIX + pix;
        xp[0*PIX] = f2h2(acc[0], acc[1]);
        xp[1*PIX] = f2h2(acc[2], acc[3]);
        xp[2*PIX] = f2h2(acc[4], acc[5]);
        xp[3*PIX] = f2h2(acc[6], acc[7]);
        xp[4*PIX] = f2h2(acc[8], 1.0f);
        xp[5*PIX] = f2h2(em[0], em[1]);
        xp[6*PIX] = f2h2(em[2], em[3]);
        xp[7*PIX] = f2h2(em[4], em[5]);
    }
}

// ---------------------------------------------------------------------------
// conv3x3 64->64, pad 1, ReLU. fp16 m16n8k16 mma, tap-major K, reg-prefetch
// pipeline. Chunk = 16 ic (8 half2 pairs) x 9 taps = 9 k16-steps; 4 chunks.
// ---------------------------------------------------------------------------
__global__ __launch_bounds__(288, 2)
void k_conv3_mma(const unsigned* __restrict__ in, const uint2* __restrict__ wp,
                 const float* __restrict__ bias, unsigned* __restrict__ out) {
    int tile = blockIdx.x;           // 0..17 row-tile
    int n = blockIdx.y;
    int r0 = tile * 4;
    int t = threadIdx.x;
    int warp = t >> 5, lane = t & 31;
    int g = lane >> 2, tig = lane & 3;

    __shared__ unsigned s_xh[8][6][76];  // pair stride 456 words (456%32==8)
    __shared__ uint2 s_wf[2304];         // [ks][o][lane]

    float acc[2][8][4];
    #pragma unroll
    for (int a = 0; a < 2; a++)
        #pragma unroll
        for (int o = 0; o < 8; o++)
            #pragma unroll
            for (int k = 0; k < 4; k++) acc[a][o][k] = 0.f;

    int prow[2][2], pcol[2][2];
    unsigned axoff[2][2];
    #pragma unroll
    for (int t2 = 0; t2 < 2; t2++)
        #pragma unroll
        for (int gi = 0; gi < 2; gi++) {
            int p = warp*32 + t2*16 + g + gi*8;   // 0..287
            prow[t2][gi] = p / 72;
            pcol[t2][gi] = p % 72;
            axoff[t2][gi] = tig*456 + prow[t2][gi]*76 + pcol[t2][gi];
        }
    const unsigned* sx = &s_xh[0][0][0];

    const unsigned* inb = in + (size_t)n * 32 * PIX;

    // hoisted input-loader tuples (2 per thread; 444 slots)
    int li_rr[2], li_cx[2];
    const unsigned* li_p[2];
    bool li_v[2], li_a[2];
    #pragma unroll
    for (int q2 = 0; q2 < 2; q2++) {
        int idx = t + q2*288;
        li_a[q2] = idx < 444;
        int rr = idx / 74, cx = idx % 74;
        int cc2 = cx - 1, gi2 = r0 + rr - 1;
        li_rr[q2] = rr; li_cx[q2] = cx;
        li_v[q2] = li_a[q2] && cc2 >= 0 && cc2 < 72 && gi2 >= 0 && gi2 < 72;
        li_p[q2] = li_v[q2] ? (inb + gi2*72 + cc2) : inb;
    }

    unsigned pinv[2][8];
    uint2 pw[8];

    // ---- prologue: chunk 0 (pairs 0..7) ----
    #pragma unroll
    for (int j = 0; j < 8; j++) pw[j] = wp[t + j*288];
    #pragma unroll
    for (int q2 = 0; q2 < 2; q2++)
        #pragma unroll
        for (int c = 0; c < 8; c++)
            pinv[q2][c] = li_v[q2] ? __ldg(li_p[q2] + (size_t)c * PIX) : 0u;
    #pragma unroll
    for (int j = 0; j < 8; j++) s_wf[t + j*288] = pw[j];
    #pragma unroll
    for (int q2 = 0; q2 < 2; q2++)
        if (li_a[q2]) {
            #pragma unroll
            for (int c = 0; c < 8; c++)
                s_xh[c][li_rr[q2]][li_cx[q2]] = pinv[q2][c];
        }
    __syncthreads();

    for (int cc = 0; cc < 4; cc++) {
        bool more = cc < 3;
        if (more) {
            const uint2* wpn = wp + (cc+1)*2304;
            #pragma unroll
            for (int j = 0; j < 8; j++) pw[j] = wpn[t + j*288];
            int p0 = (cc+1)*8;
            #pragma unroll
            for (int q2 = 0; q2 < 2; q2++)
                #pragma unroll
                for (int c = 0; c < 8; c++)
                    pinv[q2][c] = li_v[q2] ? __ldg(li_p[q2] + (size_t)(p0+c) * PIX) : 0u;
        }
        // ---- compute chunk cc: 9 k16-steps ----
        #pragma unroll
        for (int ks = 0; ks < 9; ks++) {
            const int off = (ks/3)*76 + (ks%3);
            unsigned av[2][4];
            #pragma unroll
            for (int t2 = 0; t2 < 2; t2++)
                #pragma unroll
                for (int gi = 0; gi < 2; gi++) {
                    av[t2][gi]     = sx[axoff[t2][gi] + off];           // pair tig
                    av[t2][2 + gi] = sx[axoff[t2][gi] + 4*456 + off];   // pair tig+4
                }
            #pragma unroll
            for (int o = 0; o < 8; o++) {
                uint2 b = s_wf[ks*256 + o*32 + lane];
                mma_f16(acc[0][o], av[0], b.x, b.y);
                mma_f16(acc[1][o], av[1], b.x, b.y);
            }
        }
        __syncthreads();
        if (more) {
            #pragma unroll
            for (int j = 0; j < 8; j++) s_wf[t + j*288] = pw[j];
            #pragma unroll
            for (int q2 = 0; q2 < 2; q2++)
                if (li_a[q2]) {
                    #pragma unroll
                    for (int c = 0; c < 8; c++)
                        s_xh[c][li_rr[q2]][li_cx[q2]] = pinv[q2][c];
                }
            __syncthreads();
        }
    }

    // ---- epilogue: bias + ReLU, channel-paired half2 store ----
    unsigned* outb = out + (size_t)n * 32 * PIX;
    #pragma unroll
    for (int o = 0; o < 8; o++) {
        int oc0 = o*8 + 2*tig;
        float bv0 = bias[oc0], bv1 = bias[oc0 + 1];
        #pragma unroll
        for (int t2 = 0; t2 < 2; t2++) {
            #pragma unroll
            for (int gi = 0; gi < 2; gi++) {
                int gr = r0 + prow[t2][gi];
                int gc = pcol[t2][gi];
                float v0 = fmaxf(acc[t2][o][gi*2 + 0] + bv0, 0.f);
                float v1 = fmaxf(acc[t2][o][gi*2 + 1] + bv1, 0.f);
                outb[(size_t)(o*4 + tig) * PIX + gr*72 + gc] = f2h2(v0, v1);
            }
        }
    }
}

// ---------------------------------------------------------------------------
// conv5x5 16->64, pad 2, ReLU. fp16 m16n8k16. Chunk = 8 ic (4 pairs);
// k16-step = taps (2ks,2ks+1) x 8 ic; 13 steps (tap 25 zero-padded); 2 chunks.
// ---------------------------------------------------------------------------
__global__ __launch_bounds__(288, 2)
void k_conv5_mma(const unsigned* __restrict__ in, const uint2* __restrict__ wp,
                 const float* __restrict__ bias, unsigned* __restrict__ out) {
    int tile = blockIdx.x;
    int n = blockIdx.y;
    int r0 = tile * 4;
    int t = threadIdx.x;
    int warp = t >> 5, lane = t & 31;
    int g = lane >> 2, tig = lane & 3;

    __shared__ unsigned s_xh[4][8][77];  // pair stride 616 (616%32==8)
    __shared__ uint2 s_wf[3328];         // [ks(13)][o][lane]

    float acc[2][8][4];
    #pragma unroll
    for (int a = 0; a < 2; a++)
        #pragma unroll
        for (int o = 0; o < 8; o++)
            #pragma unroll
            for (int k = 0; k < 4; k++) acc[a][o][k] = 0.f;

    int prow[2][2], pcol[2][2];
    unsigned axoff[2][2];
    #pragma unroll
    for (int t2 = 0; t2 < 2; t2++)
        #pragma unroll
        for (int gi = 0; gi < 2; gi++) {
            int p = warp*32 + t2*16 + g + gi*8;
            prow[t2][gi] = p / 72;
            pcol[t2][gi] = p % 72;
            axoff[t2][gi] = tig*616 + prow[t2][gi]*77 + pcol[t2][gi];
        }
    const unsigned* sx = &s_xh[0][0][0];

    const unsigned* inb = in + (size_t)n * 8 * PIX;

    // loader tuples: 608 slots = 8 rows x 76 cols; 3 per thread
    int li_rr[3], li_cx[3];
    const unsigned* li_p[3];
    bool li_v[3], li_a[3];
    #pragma unroll
    for (int q2 = 0; q2 < 3; q2++) {
        int idx = t + q2*288;
        li_a[q2] = idx < 608;
        int rr = idx / 76, cx = idx % 76;
        int cc2 = cx - 2, gi2 = r0 + rr - 2;
        li_rr[q2] = rr; li_cx[q2] = cx;
        li_v[q2] = li_a[q2] && cc2 >= 0 && cc2 < 72 && gi2 >= 0 && gi2 < 72;
        li_p[q2] = li_v[q2] ? (inb + gi2*72 + cc2) : inb;
    }

    unsigned pinv[3][4];

    // prologue: chunk 0 (pairs 0..3)
    #pragma unroll
    for (int q2 = 0; q2 < 3; q2++)
        #pragma unroll
        for (int c = 0; c < 4; c++)
            pinv[q2][c] = li_v[q2] ? __ldg(li_p[q2] + (size_t)c * PIX) : 0u;
    #pragma unroll
    for (int j = 0; j < 12; j++) {
        int idx = t + j*288;
        if (idx < 3328) s_wf[idx] = wp[idx];
    }
    #pragma unroll
    for (int q2 = 0; q2 < 3; q2++)
        if (li_a[q2]) {
            #pragma unroll
            for (int c = 0; c < 4; c++)
                s_xh[c][li_rr[q2]][li_cx[q2]] = pinv[q2][c];
        }
    __syncthreads();

    for (int cc = 0; cc < 2; cc++) {
        bool more = cc < 1;
        if (more) {
            #pragma unroll
            for (int q2 = 0; q2 < 3; q2++)
                #pragma unroll
                for (int c = 0; c < 4; c++)
                    pinv[q2][c] = li_v[q2] ? __ldg(li_p[q2] + (size_t)(4+c) * PIX) : 0u;
        }
        #pragma unroll
        for (int ks = 0; ks < 13; ks++) {
            const int tap0 = 2*ks;
            const int tap1 = (2*ks + 1 < 25) ? (2*ks + 1) : 24;  // B zero at pad
            const int off0 = (tap0/5)*77 + (tap0%5);
            const int off1 = (tap1/5)*77 + (tap1%5);
            unsigned av[2][4];
            #pragma unroll
            for (int t2 = 0; t2 < 2; t2++)
                #pragma unroll
                for (int gi = 0; gi < 2; gi++) {
                    av[t2][gi]     = sx[axoff[t2][gi] + off0];   // pair tig, tap0
                    av[t2][2 + gi] = sx[axoff[t2][gi] + off1];   // pair tig, tap1
                }
            #pragma unroll
            for (int o = 0; o < 8; o++) {
                uint2 b = s_wf[ks*256 + o*32 + lane];
                mma_f16(acc[0][o], av[0], b.x, b.y);
                mma_f16(acc[1][o], av[1], b.x, b.y);
            }
        }
        __syncthreads();
        if (more) {
            const uint2* wpn = wp + 3328;
            #pragma unroll
            for (int j = 0; j < 12; j++) {
                int idx = t + j*288;
                if (idx < 3328) s_wf[idx] = wpn[idx];
            }
            #pragma unroll
            for (int q2 = 0; q2 < 3; q2++)
                if (li_a[q2]) {
                    #pragma unroll
                    for (int c = 0; c < 4; c++)
                        s_xh[c][li_rr[q2]][li_cx[q2]] = pinv[q2][c];
                }
            __syncthreads();
        }
    }

    unsigned* outb = out + (size_t)n * 32 * PIX;
    #pragma unroll
    for (int o = 0; o < 8; o++) {
        int oc0 = o*8 + 2*tig;
        float bv0 = bias[oc0], bv1 = bias[oc0 + 1];
        #pragma unroll
        for (int t2 = 0; t2 < 2; t2++) {
            #pragma unroll
            for (int gi = 0; gi < 2; gi++) {
                int gr = r0 + prow[t2][gi];
                int gc = pcol[t2][gi];
                float v0 = fmaxf(acc[t2][o][gi*2 + 0] + bv0, 0.f);
                float v1 = fmaxf(acc[t2][o][gi*2 + 1] + bv1, 0.f);
                outb[(size_t)(o*4 + tig) * PIX + gr*72 + gc] = f2h2(v0, v1);
            }
        }
    }
}

// ---------------------------------------------------------------------------
// Per-room window pooling (input is channel-paired half2)
// ---------------------------------------------------------------------------
__global__ void k_feat(const unsigned* __restrict__ Xh, const float* __restrict__ rt,
                       const int* __restrict__ pos, float* __restrict__ feat) {
    int b = blockIdx.x;            // n*32 + r
    int n = b >> 5, r = b & 31;
    int c = threadIdx.x;           // 0..63
    __shared__ float s_rm[48];
    if (c < 48) s_rm[c] = rt[r*9*48 + c];   // channel 0 = room_map
    __syncthreads();
    float rsum = 0.f;
    #pragma unroll
    for (int k = 0; k < 48; k++) rsum += s_rm[k];
    int px = pos[b*2], py = pos[b*2+1];
    const unsigned* xp = Xh + ((size_t)n*32 + (c >> 1))*PIX + px*72 + py;
    int hi = c & 1;
    float acc = 0.f;
    #pragma unroll
    for (int w = 0; w < WW; w++)
        #pragma unroll
        for (int h = 0; h < HH; h++) {
            unsigned u = xp[w*72 + h];
            __half2 hv = *reinterpret_cast<const __half2*>(&u);
            float val = hi ? __high2float(hv) : __low2float(hv);
            acc += s_rm[w*HH + h] * val;
        }
    feat[b*64 + c] = acc / rsum;
}

// ---------------------------------------------------------------------------
// Per-room MLP 64->128->128 (ReLU), summed over rooms. 4 rooms per pass.
// ---------------------------------------------------------------------------
__global__ __launch_bounds__(128)
void k_room(const float* __restrict__ feat, const float* __restrict__ wt,
            const float* __restrict__ b1, const float* __restrict__ b2,
            float* __restrict__ S) {
    const float* w1t = wt;          // [64][128]
    const float* w2t = wt + 8192;   // [128][128]
    int n = blockIdx.x;
    int o = threadIdx.x;
    __shared__ float s_f[4][64];
    __shared__ float s_h1[4][128];
    float accS = 0.f;
    float bb1 = b1[o], bb2 = b2[o];
    for (int rg = 0; rg < 8; rg++) {
        #pragma unroll
        for (int i = o; i < 256; i += 128) {
            int r = i >> 6, c = i & 63;
            s_f[r][c] = feat[(n*RROOM + rg*4 + r)*64 + c];
        }
        __syncthreads();
        float a0 = bb1, a1 = bb1, a2 = bb1, a3 = bb1;
        #pragma unroll
        for (int c = 0; c < 64; c++) {
            float wv = w1t[c*128 + o];
            a0 += wv * s_f[0][c]; a1 += wv * s_f[1][c];
            a2 += wv * s_f[2][c]; a3 += wv * s_f[3][c];
        }
        s_h1[0][o] = fmaxf(a0, 0.f); s_h1[1][o] = fmaxf(a1, 0.f);
        s_h1[2][o] = fmaxf(a2, 0.f); s_h1[3][o] = fmaxf(a3, 0.f);
        __syncthreads();
        float z0 = bb2, z1 = bb2, z2 = bb2, z3 = bb2;
        #pragma unroll
        for (int c = 0; c < 128; c++) {
            float wv = w2t[c*128 + o];
            z0 += wv * s_h1[0][c]; z1 += wv * s_h1[1][c];
            z2 += wv * s_h1[2][c]; z3 += wv * s_h1[3][c];
        }
        accS += fmaxf(z0, 0.f) + fmaxf(z1, 0.f) + fmaxf(z2, 0.f) + fmaxf(z3, 0.f);
        __syncthreads();
    }
    S[n*128 + o] = accS;
}

// ---------------------------------------------------------------------------
// FC head: 128->256 ReLU -> 256->256. 4 images per block.
// ---------------------------------------------------------------------------
__global__ __launch_bounds__(256)
void k_fc(const float* __restrict__ S, const float* __restrict__ wt,
          const float* __restrict__ bf1, const float* __restrict__ bf2,
          float* __restrict__ out) {
    const float* wf1t = wt + 24576;  // [128][256]
    const float* wf2t = wt + 57344;  // [256][256]
    int n0 = blockIdx.x * 4;
    int o = threadIdx.x;
    __shared__ float s_in[4][128];
    __shared__ float s_h[4][256];
    #pragma unroll
    for (int i = o; i < 512; i += 256) {
        int q = i >> 7, c = i & 127;
        s_in[q][c] = S[(n0 + q)*128 + c];
    }
    __syncthreads();
    float a0 = bf1[o], a1 = a0, a2 = a0, a3 = a0;
    #pragma unroll
    for (int c = 0; c < 128; c++) {
        float wv = wf1t[c*256 + o];
        a0 += wv * s_in[0][c]; a1 += wv * s_in[1][c];
        a2 += wv * s_in[2][c]; a3 += wv * s_in[3][c];
    }
    s_h[0][o] = fmaxf(a0, 0.f); s_h[1][o] = fmaxf(a1, 0.f);
    s_h[2][o] = fmaxf(a2, 0.f); s_h[3][o] = fmaxf(a3, 0.f);
    __syncthreads();
    float z0 = bf2[o], z1 = z0, z2 = z0, z3 = z0;
    #pragma unroll
    for (int c = 0; c < 256; c++) {
        float wv = wf2t[c*256 + o];
        z0 += wv * s_h[0][c]; z1 += wv * s_h[1][c];
        z2 += wv * s_h[2][c]; z3 += wv * s_h[3][c];
    }
    out[(n0 + 0)*256 + o] = z0;
    out[(n0 + 1)*256 + o] = z1;
    out[(n0 + 2)*256 + o] = z2;
    out[(n0 + 3)*256 + o] = z3;
}

extern "C" void kernel_launch(void* const* d_in, const int* in_sizes, int n_in,
                              void* d_out, int out_size) {
    const int*   pos = (const int*)d_in[0];
    const float* rt  = (const float*)d_in[1];
    const float* emb = (const float*)d_in[2];
    const float* w1  = (const float*)d_in[3];
    const float* b1  = (const float*)d_in[4];
    const float* w2  = (const float*)d_in[5];
    const float* b2  = (const float*)d_in[6];
    const float* w3  = (const float*)d_in[7];
    const float* b3  = (const float*)d_in[8];
    const float* wr1 = (const float*)d_in[9];
    const float* br1 = (const float*)d_in[10];
    const float* wr2 = (const float*)d_in[11];
    const float* br2 = (const float*)d_in[12];
    const float* wf1 = (const float*)d_in[13];
    const float* bf1 = (const float*)d_in[14];
    const float* wf2 = (const float*)d_in[15];
    const float* bf2 = (const float*)d_in[16];
    float* out = (float*)d_out;

    unsigned *X0h, *XAh, *XBh;
    float *feat, *S, *wt;
    uint2 *wpk;
    cudaGetSymbolAddress((void**)&X0h, g_X0h);
    cudaGetSymbolAddress((void**)&XAh, g_XAh);
    cudaGetSymbolAddress((void**)&XBh, g_XBh);
    cudaGetSymbolAddress((void**)&feat, g_feat);
    cudaGetSymbolAddress((void**)&S, g_S);
    cudaGetSymbolAddress((void**)&wt, g_wt);
    cudaGetSymbolAddress((void**)&wpk, g_wp);

    k_prep<<<96, 256>>>(w1, w2, w3, wr1, wr2, wf1, wf2, wt, wpk);
    k_build<<<dim3(4, NIMG), 256>>>(pos, rt, emb, X0h);
    k_conv5_mma<<<dim3(18, NIMG), 288>>>(X0h, wpk, b1, XAh);
    k_conv3_mma<<<dim3(18, NIMG), 288>>>(XAh, wpk + 6656, b2, XBh);
    k_conv3_mma<<<dim3(18, NIMG), 288>>>(XBh, wpk + 15872, b3, XAh);
    k_feat<<<NIMG*RROOM, 64>>>(XAh, rt, pos, feat);
    k_room<<<NIMG, 128>>>(feat, wt, br1, br2, S);
    k_fc<<<NIMG/4, 256>>>(S, wt, bf1, bf2, out);
}